// round 10
// baseline (speedup 1.0000x reference)
#include <cuda_runtime.h>
#include <cuda_fp16.h>
#include <cstdint>
#include <math.h>

// Problem constants
#define B_   8
#define S_   1024      // H*W
#define E_   256
#define CS_  128
#define CT_  256
#define NH_  8
#define HD_  32

// ---------------- scratch (static device memory; no allocations) ----------------
__device__ uint32_t g_Wq_t [E_ * E_];        // tf32 bits of in_proj_w[:E]
__device__ uint32_t g_Wk2_t[E_ * CS_];       // tf32 bits of Wk @ kv_w
__device__ uint32_t g_Wv2_t[E_ * CS_];       // tf32 bits of Wv @ kv_w
__device__ uint32_t g_Mw_t [CT_ * E_];       // tf32 bits of fuse_w @ out_proj_w
__device__ float    g_fb   [CT_];            // fuse_w @ out_proj_b
__device__ uint32_t g_Q  [B_ * NH_ * S_ * HD_]; // tf32 bits, [b][h][s][d]
__device__ uint32_t g_K  [B_ * NH_ * S_ * HD_];
__device__ __half   g_Vh [B_ * NH_ * HD_ * S_]; // fp16, TRANSPOSED [b][h][d][s]
__device__ float    g_ctx[B_ * S_ * E_];        // [b][s][e] fp32
__device__ float    g_linv[B_ * NH_ * S_];      // 1/l per (bh, q)
__device__ uint32_t g_Es[(size_t)B_ * NH_ * S_ * S_ / 2]; // fp16x2 unnormalized e, [bh][q][k/2]

// ---------------- helpers ----------------
__device__ __forceinline__ uint32_t f2tf32(float x) {
    uint32_t r;
    asm("cvt.rna.tf32.f32 %0, %1;" : "=r"(r) : "f"(x));
    return r;
}
__device__ __forceinline__ void mma_tf32(float d[4], const uint32_t a[4],
                                         const uint32_t b[2], const float c[4]) {
    asm volatile(
        "mma.sync.aligned.m16n8k8.row.col.f32.tf32.tf32.f32 "
        "{%0,%1,%2,%3}, {%4,%5,%6,%7}, {%8,%9}, {%10,%11,%12,%13};"
        : "=f"(d[0]), "=f"(d[1]), "=f"(d[2]), "=f"(d[3])
        : "r"(a[0]), "r"(a[1]), "r"(a[2]), "r"(a[3]),
          "r"(b[0]), "r"(b[1]),
          "f"(c[0]), "f"(c[1]), "f"(c[2]), "f"(c[3]));
}
__device__ __forceinline__ void mma_f16(float d[4], const uint32_t a[4],
                                        const uint32_t b[2], const float c[4]) {
    asm volatile(
        "mma.sync.aligned.m16n8k16.row.col.f32.f16.f16.f32 "
        "{%0,%1,%2,%3}, {%4,%5,%6,%7}, {%8,%9}, {%10,%11,%12,%13};"
        : "=f"(d[0]), "=f"(d[1]), "=f"(d[2]), "=f"(d[3])
        : "r"(a[0]), "r"(a[1]), "r"(a[2]), "r"(a[3]),
          "r"(b[0]), "r"(b[1]),
          "f"(c[0]), "f"(c[1]), "f"(c[2]), "f"(c[3]));
}
__device__ __forceinline__ uint32_t pack_h2(float lo, float hi) {
    __half2 h = __floats2half2_rn(lo, hi);
    return *reinterpret_cast<uint32_t*>(&h);
}

// ---------------- kernel 0: fold weight chains -> tf32 bits, zero attn map ----------------
__global__ void k_combine(const float* __restrict__ in_proj_w,
                          const float* __restrict__ kv_w,
                          const float* __restrict__ fuse_w,
                          const float* __restrict__ out_proj_w,
                          const float* __restrict__ out_proj_b,
                          float* __restrict__ out_attn) {
    int idx = blockIdx.x * blockDim.x + threadIdx.x;
    const int N1 = E_ * CS_;          // 32768  Wk2
    const int N2 = 2 * N1;            // 65536  Wv2
    const int N3 = N2 + CT_ * E_;     // 131072 Mw
    const int N4 = N3 + CT_;          // 131328 fb
    const int N5 = N4 + E_ * E_;      // 196864 Wq bits
    const int N6 = N5 + B_ * S_;      // 205056 attn zero
    if (idx < N1) {
        int f = idx / CS_, c = idx % CS_;
        float s = 0.f;
        for (int e = 0; e < E_; e++)
            s += in_proj_w[(E_ + f) * E_ + e] * kv_w[e * CS_ + c];
        g_Wk2_t[idx] = f2tf32(s);
    } else if (idx < N2) {
        int j = idx - N1;
        int f = j / CS_, c = j % CS_;
        float s = 0.f;
        for (int e = 0; e < E_; e++)
            s += in_proj_w[(2 * E_ + f) * E_ + e] * kv_w[e * CS_ + c];
        g_Wv2_t[j] = f2tf32(s);
    } else if (idx < N3) {
        int j = idx - N2;
        int cc = j / E_, ep = j % E_;
        float s = 0.f;
        for (int e = 0; e < E_; e++)
            s += fuse_w[cc * E_ + e] * out_proj_w[e * E_ + ep];
        g_Mw_t[j] = f2tf32(s);
    } else if (idx < N4) {
        int cc = idx - N3;
        float s = 0.f;
        for (int e = 0; e < E_; e++)
            s += fuse_w[cc * E_ + e] * out_proj_b[e];
        g_fb[cc] = s;
    } else if (idx < N5) {
        int j = idx - N4;
        g_Wq_t[j] = f2tf32(in_proj_w[j]);
    } else if (idx < N6) {
        out_attn[idx - N5] = 0.f;
    }
}

// ---------------- kernel 1: Q/K/V projection, tf32 MMA (merged 3-way) ----------------
// blockIdx.z: which = z>>3 (0=Q,1=K,2=V), b = z&7
// Q,K stored as tf32 bits [bh][s][d]; V stored fp16 TRANSPOSED [bh][d][s].
__global__ void __launch_bounds__(256) k_proj(const float* __restrict__ tgt,
                                              const float* __restrict__ src,
                                              const float* __restrict__ in_proj_b) {
    __shared__ uint32_t As[32 * 68];   // [c][s] tf32 bits
    __shared__ uint32_t Bs[64 * 36];   // [e][c] tf32 bits
    int which = blockIdx.z >> 3;
    int b = blockIdx.z & 7;
    const uint32_t* W = (which == 0) ? g_Wq_t : (which == 1 ? g_Wk2_t : g_Wv2_t);
    const float* In = (which == 0) ? tgt : src;
    const float* bias = in_proj_b + which * E_;
    int Cin = (which == 0) ? CT_ : CS_;

    int s0 = blockIdx.x * 64, e0 = blockIdx.y * 64;
    int tid = threadIdx.x;
    int lane = tid & 31, w = tid >> 5;
    int gid = lane >> 2, tig = lane & 3;
    int mw = w >> 1, nh = w & 1;   // s block of 16, e half of 32
    const float* Ab = In + (size_t)b * Cin * S_;

    int sl = tid & 63, cl0 = tid >> 6;    // A loader coords
    int clB = tid & 31, el0 = tid >> 5;   // B loader coords

    float acc[4][4] = {};
    int nchunks = Cin >> 5;
    for (int ch = 0; ch < nchunks; ch++) {
        int c0 = ch << 5;
        __syncthreads();
        #pragma unroll
        for (int r = 0; r < 8; r++) {
            int cl = cl0 + 4 * r;
            As[cl * 68 + sl] = f2tf32(Ab[(size_t)(c0 + cl) * S_ + s0 + sl]);
        }
        #pragma unroll
        for (int r = 0; r < 8; r++) {
            int el = el0 + 8 * r;
            Bs[el * 36 + clB] = W[(size_t)(e0 + el) * Cin + c0 + clB];
        }
        __syncthreads();
        #pragma unroll
        for (int ks = 0; ks < 4; ks++) {
            uint32_t a[4];
            int sr = 16 * mw + gid;
            int cc = 8 * ks + tig;
            a[0] = As[cc * 68 + sr];
            a[1] = As[cc * 68 + sr + 8];
            a[2] = As[(cc + 4) * 68 + sr];
            a[3] = As[(cc + 4) * 68 + sr + 8];
            #pragma unroll
            for (int nt = 0; nt < 4; nt++) {
                uint32_t bb[2];
                int er = 32 * nh + 8 * nt + gid;
                bb[0] = Bs[er * 36 + 8 * ks + tig];
                bb[1] = Bs[er * 36 + 8 * ks + tig + 4];
                mma_tf32(acc[nt], a, bb, acc[nt]);
            }
        }
    }
    // epilogue
    if (which != 2) {
        uint32_t* Out = (which == 0) ? g_Q : g_K;
        #pragma unroll
        for (int nt = 0; nt < 4; nt++) {
            int e = e0 + 32 * nh + 8 * nt + 2 * tig;
            float b0 = bias[e], b1 = bias[e + 1];
            int h = e >> 5, d = e & 31;
            int s = s0 + 16 * mw + gid;
            uint32_t lo, hi;
            size_t base = (((size_t)(b * NH_ + h) * S_ + s) << 5) + d;
            lo = f2tf32(acc[nt][0] + b0); hi = f2tf32(acc[nt][1] + b1);
            *reinterpret_cast<uint2*>(&Out[base]) = make_uint2(lo, hi);
            lo = f2tf32(acc[nt][2] + b0); hi = f2tf32(acc[nt][3] + b1);
            *reinterpret_cast<uint2*>(&Out[base + (8u << 5)]) = make_uint2(lo, hi);
        }
    } else {
        // V: fp16 transposed [bh][d][s]
        #pragma unroll
        for (int nt = 0; nt < 4; nt++) {
            int e = e0 + 32 * nh + 8 * nt + 2 * tig;
            float b0 = bias[e], b1 = bias[e + 1];
            int h = e >> 5, d = e & 31;
            int s = s0 + 16 * mw + gid;
            size_t r0 = ((size_t)(b * NH_ + h) * HD_ + d) * S_;
            size_t r1 = r0 + S_;   // d+1 row (same head: d = 8nt+2tig <= 30)
            g_Vh[r0 + s]     = __float2half(acc[nt][0] + b0);
            g_Vh[r1 + s]     = __float2half(acc[nt][1] + b1);
            g_Vh[r0 + s + 8] = __float2half(acc[nt][2] + b0);
            g_Vh[r1 + s + 8] = __float2half(acc[nt][3] + b1);
        }
    }
}

// ---------------- kernel 2: fused attention, single pass, register P ----------------
// S = QK^T in tf32 MMA; exp in regs; P packed fp16x2 feeds m16n8k16 O-MMA directly
// (d-frags of two adjacent n8 S-tiles == A-frag of m16n8k16). Unnormalized e streamed
// to g_Es (gmem, fp16); l reduced at end -> linv to smem + gmem; O normalized at end.
// Warp layout: mw = q 16-block (4), nh = key 32-half (2). O partial per warp over its
// 32 keys; nh pair combined via smem at the end.
// smem words: Qs[64*36]@0, Ks[64*36]@2304, Vs[32*36]@4608, lsum@5760, linv@5824, redO@5888[2048]
// total 7936 words = 31744 B
__global__ void __launch_bounds__(256, 2) k_attn() {
    extern __shared__ uint32_t sm[];
    uint32_t* Qs = sm;
    uint32_t* Ks = sm + 2304;
    uint32_t* Vs = sm + 4608;           // [d][key-pair words], stride 36
    float* lsum  = (float*)(sm + 5760);
    float* linv  = (float*)(sm + 5824);
    float* redO  = (float*)(sm + 5888); // [mw][nj][16][8]

    int bh = blockIdx.y;
    int b = bh >> 3, h = bh & 7;
    int q0 = blockIdx.x * 64;
    const uint32_t* Qb = g_Q + (size_t)bh * S_ * HD_;
    const uint32_t* Kb = g_K + (size_t)bh * S_ * HD_;
    const uint32_t* VhW = reinterpret_cast<const uint32_t*>(g_Vh) + (size_t)bh * HD_ * (S_ / 2);
    uint32_t* EsW = g_Es + ((size_t)bh * S_ * S_ / 2);

    int tid = threadIdx.x;
    int lane = tid & 31, w = tid >> 5;
    int gid = lane >> 2, tig = lane & 3;
    int r8 = tid >> 5, d32 = tid & 31;      // K loader coords
    int vd = tid >> 3, vw0 = tid & 7;       // V loader coords

    int mw = w >> 1, nh = w & 1;

    if (tid < 64) lsum[tid] = 0.f;

    #pragma unroll
    for (int r = 0; r < 8; r++) {
        int q = r8 + 8 * r;
        Qs[q * 36 + d32] = Qb[(size_t)(q0 + q) * HD_ + d32];
    }
    __syncthreads();

    // Q fragments, register-resident
    uint32_t aq[4][4];
    #pragma unroll
    for (int ks = 0; ks < 4; ks++) {
        int qr = 16 * mw + gid;
        int c  = ks * 8 + tig;
        aq[ks][0] = Qs[qr * 36 + c];
        aq[ks][1] = Qs[(qr + 8) * 36 + c];
        aq[ks][2] = Qs[qr * 36 + c + 4];
        aq[ks][3] = Qs[(qr + 8) * 36 + c + 4];
    }

    const float scale = 0.17677669529663687f; // 1/sqrt(32)
    float l0 = 0.f, l1 = 0.f;
    float oacc[4][4] = {};   // [nj: d 8-col tile][frag]

    // prefetch tile 0
    uint32_t kreg[8], vreg[4];
    #pragma unroll
    for (int r = 0; r < 8; r++)
        kreg[r] = Kb[(size_t)(r8 + 8 * r) * HD_ + d32];
    #pragma unroll
    for (int r = 0; r < 4; r++)
        vreg[r] = VhW[(size_t)vd * (S_ / 2) + vw0 + 8 * r];

    for (int t = 0; t < 16; t++) {
        int k0 = t * 64;
        __syncthreads();   // prior tile compute done with Ks/Vs
        #pragma unroll
        for (int r = 0; r < 8; r++)
            Ks[(r8 + 8 * r) * 36 + d32] = kreg[r];
        #pragma unroll
        for (int r = 0; r < 4; r++)
            Vs[vd * 36 + vw0 + 8 * r] = vreg[r];
        __syncthreads();
        if (t < 15) {
            int k0n = k0 + 64;
            #pragma unroll
            for (int r = 0; r < 8; r++)
                kreg[r] = Kb[(size_t)(k0n + r8 + 8 * r) * HD_ + d32];
            #pragma unroll
            for (int r = 0; r < 4; r++)
                vreg[r] = VhW[(size_t)vd * (S_ / 2) + (k0n >> 1) + vw0 + 8 * r];
        }

        // ---- S phase: tf32 MMA over this warp's 32-key half
        float sacc[4][4] = {};
        #pragma unroll
        for (int ks = 0; ks < 4; ks++) {
            #pragma unroll
            for (int nt = 0; nt < 4; nt++) {
                uint32_t bf[2];
                int key = 32 * nh + 8 * nt + gid;
                int d0  = ks * 8 + tig;
                bf[0] = Ks[key * 36 + d0];
                bf[1] = Ks[key * 36 + d0 + 4];
                mma_tf32(sacc[nt], aq[ks], bf, sacc[nt]);
            }
        }

        // ---- exp + pack + stream to gmem + row-sum partials
        uint32_t pl[4], ph[4];
        int qr = 16 * mw + gid;
        size_t esbase0 = ((size_t)(q0 + qr)) * (S_ / 2) + ((k0 + 32 * nh) >> 1) + tig;
        size_t esbase1 = esbase0 + 8 * (S_ / 2);
        #pragma unroll
        for (int nt = 0; nt < 4; nt++) {
            float e0 = __expf(sacc[nt][0] * scale);
            float e1 = __expf(sacc[nt][1] * scale);
            float e2 = __expf(sacc[nt][2] * scale);
            float e3 = __expf(sacc[nt][3] * scale);
            l0 += e0 + e1;
            l1 += e2 + e3;
            pl[nt] = pack_h2(e0, e1);
            ph[nt] = pack_h2(e2, e3);
            EsW[esbase0 + 4 * nt] = pl[nt];
            EsW[esbase1 + 4 * nt] = ph[nt];
        }

        // ---- O phase: fp16 m16n8k16, A = packed P frags (no smem roundtrip)
        #pragma unroll
        for (int c = 0; c < 2; c++) {
            uint32_t ap[4] = { pl[2 * c], ph[2 * c], pl[2 * c + 1], ph[2 * c + 1] };
            int kwb = 16 * nh + 8 * c;   // key word base within tile
            #pragma unroll
            for (int nj = 0; nj < 4; nj++) {
                uint32_t bv[2];
                int drow = 8 * nj + gid;
                bv[0] = Vs[drow * 36 + kwb + tig];
                bv[1] = Vs[drow * 36 + kwb + tig + 4];
                mma_f16(oacc[nj], ap, bv, oacc[nj]);
            }
        }
    }

    // ---- reduce row sums; linv to smem + gmem
    __syncthreads();
    atomicAdd(&lsum[16 * mw + gid], l0);
    atomicAdd(&lsum[16 * mw + gid + 8], l1);
    __syncthreads();
    if (tid < 64) {
        float li = 1.0f / lsum[tid];
        linv[tid] = li;
        g_linv[(size_t)bh * S_ + q0 + tid] = li;
    }
    __syncthreads();

    // ---- combine nh warp pairs, normalize, write ctx
    if (nh == 1) {
        #pragma unroll
        for (int nj = 0; nj < 4; nj++) {
            float* rb = &redO[((mw * 4 + nj) * 16) * 8];
            rb[gid * 8 + 2 * tig]           = oacc[nj][0];
            rb[gid * 8 + 2 * tig + 1]       = oacc[nj][1];
            rb[(gid + 8) * 8 + 2 * tig]     = oacc[nj][2];
            rb[(gid + 8) * 8 + 2 * tig + 1] = oacc[nj][3];
        }
    }
    __syncthreads();
    if (nh == 0) {
        int qr = 16 * mw + gid;
        float li0 = linv[qr], li1 = linv[qr + 8];
        #pragma unroll
        for (int nj = 0; nj < 4; nj++) {
            const float* rb = &redO[((mw * 4 + nj) * 16) * 8];
            float o0 = (oacc[nj][0] + rb[gid * 8 + 2 * tig]) * li0;
            float o1 = (oacc[nj][1] + rb[gid * 8 + 2 * tig + 1]) * li0;
            float o2 = (oacc[nj][2] + rb[(gid + 8) * 8 + 2 * tig]) * li1;
            float o3 = (oacc[nj][3] + rb[(gid + 8) * 8 + 2 * tig + 1]) * li1;
            int d = h * HD_ + 8 * nj + 2 * tig;
            *reinterpret_cast<float2*>(
                &g_ctx[((size_t)b * S_ + q0 + qr) * E_ + d]) = make_float2(o0, o1);
            *reinterpret_cast<float2*>(
                &g_ctx[((size_t)b * S_ + q0 + qr + 8) * E_ + d]) = make_float2(o2, o3);
        }
    }
}

// ---------------- kernel 3: attn map column sums from streamed e ----------------
// out_attn[b][k] = (1/8192) * sum_{h,q} e[bh][q][k] * linv[bh][q]
// grid (8, 4, 16), block 128: thread handles key pair k2, sums 512 (h,q)-rows.
__global__ void __launch_bounds__(128) k_amap(float* __restrict__ out_attn) {
    int b = blockIdx.x, kc = blockIdx.y, qc = blockIdx.z;
    int k2 = kc * 128 + threadIdx.x;            // key-pair index (keys 2k2, 2k2+1)
    const uint32_t* Eb = g_Es + ((size_t)b * NH_ * S_) * (S_ / 2);
    const float* Lb = g_linv + (size_t)b * NH_ * S_;
    float a0 = 0.f, a1 = 0.f;
    int rr0 = qc * 512;
    #pragma unroll 4
    for (int i = 0; i < 512; i++) {
        int rr = rr0 + i;
        float li = Lb[rr];
        uint32_t u = Eb[(size_t)rr * (S_ / 2) + k2];
        __half2 h = *reinterpret_cast<__half2*>(&u);
        float2 f = __half22float2(h);
        a0 = fmaf(f.x, li, a0);
        a1 = fmaf(f.y, li, a1);
    }
    const float sc = 1.0f / 8192.0f;
    atomicAdd(&out_attn[b * S_ + 2 * k2],     a0 * sc);
    atomicAdd(&out_attn[b * S_ + 2 * k2 + 1], a1 * sc);
}

// ---------------- kernel 4: fuse + BN + SiLU + residual, tf32 MMA ----------------
__global__ void __launch_bounds__(256) k_fuse(const float* __restrict__ tgt,
                       const float* __restrict__ gamma,
                       const float* __restrict__ beta,
                       const float* __restrict__ mean,
                       const float* __restrict__ var,
                       float* __restrict__ out) {
    __shared__ uint32_t As[64 * 36];  // Mw bits [c][e-chunk]
    __shared__ uint32_t Bs[64 * 36];  // ctx bits [s][e-chunk]
    int b = blockIdx.z;
    int c0 = blockIdx.x * 64, s0 = blockIdx.y * 64;
    const float* Cb = g_ctx + (size_t)b * S_ * E_;
    int tid = threadIdx.x;
    int lane = tid & 31, w = tid >> 5;
    int gid = lane >> 2, tig = lane & 3;
    int mw = w >> 1, nh = w & 1;
    int el = tid & 31, rl0 = tid >> 5;

    float acc[4][4] = {};
    #pragma unroll 1
    for (int ch = 0; ch < 8; ch++) {
        int e0 = ch << 5;
        __syncthreads();
        #pragma unroll
        for (int r = 0; r < 8; r++) {
            int row = rl0 + 8 * r;
            As[row * 36 + el] = g_Mw_t[(size_t)(c0 + row) * E_ + e0 + el];
            Bs[row * 36 + el] = f2tf32(Cb[(size_t)(s0 + row) * E_ + e0 + el]);
        }
        __syncthreads();
        #pragma unroll
        for (int ks = 0; ks < 4; ks++) {
            uint32_t a[4];
            int cr = 16 * mw + gid;
            int ec = 8 * ks + tig;
            a[0] = As[cr * 36 + ec];
            a[1] = As[(cr + 8) * 36 + ec];
            a[2] = As[cr * 36 + ec + 4];
            a[3] = As[(cr + 8) * 36 + ec + 4];
            #pragma unroll
            for (int nt = 0; nt < 4; nt++) {
                uint32_t bb[2];
                int sr = 32 * nh + 8 * nt + gid;
                bb[0] = Bs[sr * 36 + ec];
                bb[1] = Bs[sr * 36 + ec + 4];
                mma_tf32(acc[nt], a, bb, acc[nt]);
            }
        }
    }
    int c = c0 + 16 * mw + gid;
    float inv0 = gamma[c] * rsqrtf(var[c] + 1e-5f);
    float mu0 = mean[c], bet0 = beta[c], fb0 = g_fb[c];
    float inv1 = gamma[c + 8] * rsqrtf(var[c + 8] + 1e-5f);
    float mu1 = mean[c + 8], bet1 = beta[c + 8], fb1 = g_fb[c + 8];
    #pragma unroll
    for (int nt = 0; nt < 4; nt++) {
        int s = s0 + 32 * nh + 8 * nt + 2 * tig;
        size_t off0 = (size_t)b * (CT_ * S_) + (size_t)c * S_ + s;
        size_t off1 = off0 + (size_t)8 * S_;
        float2 t0 = *reinterpret_cast<const float2*>(&tgt[off0]);
        float2 t1 = *reinterpret_cast<const float2*>(&tgt[off1]);
        float bn, sg;
        float2 y0, y1;
        bn = (acc[nt][0] + fb0 - mu0) * inv0 + bet0;
        sg = 1.0f / (1.0f + __expf(-bn)); y0.x = t0.x + bn * sg;
        bn = (acc[nt][1] + fb0 - mu0) * inv0 + bet0;
        sg = 1.0f / (1.0f + __expf(-bn)); y0.y = t0.y + bn * sg;
        bn = (acc[nt][2] + fb1 - mu1) * inv1 + bet1;
        sg = 1.0f / (1.0f + __expf(-bn)); y1.x = t1.x + bn * sg;
        bn = (acc[nt][3] + fb1 - mu1) * inv1 + bet1;
        sg = 1.0f / (1.0f + __expf(-bn)); y1.y = t1.y + bn * sg;
        *reinterpret_cast<float2*>(&out[off0]) = y0;
        *reinterpret_cast<float2*>(&out[off1]) = y1;
    }
}

// ---------------- host launch ----------------
extern "C" void kernel_launch(void* const* d_in, const int* in_sizes, int n_in,
                              void* d_out, int out_size) {
    const float* tgt        = (const float*)d_in[0];
    const float* src        = (const float*)d_in[1];
    const float* kv_w       = (const float*)d_in[2];
    const float* in_proj_w  = (const float*)d_in[3];
    const float* in_proj_b  = (const float*)d_in[4];
    const float* out_proj_w = (const float*)d_in[5];
    const float* out_proj_b = (const float*)d_in[6];
    const float* fuse_w     = (const float*)d_in[7];
    const float* bn_gamma   = (const float*)d_in[8];
    const float* bn_beta    = (const float*)d_in[9];
    const float* bn_mean    = (const float*)d_in[10];
    const float* bn_var     = (const float*)d_in[11];

    float* out_y    = (float*)d_out;                         // B*Ct*H*W
    float* out_attn = (float*)d_out + (size_t)B_ * CT_ * S_; // B*H*W

    static const int ATTN_SMEM = 31744;

    // 0. fold weights -> tf32 bit matrices, zero attn map
    k_combine<<<(205056 + 255) / 256, 256>>>(in_proj_w, kv_w, fuse_w,
                                             out_proj_w, out_proj_b, out_attn);

    // 1. Q/K/V projections in one launch (tf32 MMA)
    dim3 gp(S_ / 64, E_ / 64, 3 * B_);
    k_proj<<<gp, 256>>>(tgt, src, in_proj_b);

    // 2. fused single-pass tensor-core attention (streams e + linv to gmem)
    dim3 ga(S_ / 64, B_ * NH_);
    k_attn<<<ga, 256, ATTN_SMEM>>>();

    // 3. attn map column sums
    dim3 gm(B_, 4, 16);
    k_amap<<<gm, 128>>>(out_attn);

    // 4. fuse + BN + SiLU + residual (tf32 MMA)
    dim3 gf(CT_ / 64, S_ / 64, B_);
    k_fuse<<<gf, 256>>>(tgt, bn_gamma, bn_beta, bn_mean, bn_var, out_y);
}

// round 13
// speedup vs baseline: 1.2092x; 1.2092x over previous
#include <cuda_runtime.h>
#include <cuda_fp16.h>
#include <cstdint>
#include <math.h>

// Problem constants
#define B_   8
#define S_   1024      // H*W
#define E_   256
#define CS_  128
#define CT_  256
#define NH_  8
#define HD_  32

// ---------------- scratch (static device memory; no allocations) ----------------
__device__ uint32_t g_Wq_t [E_ * E_];        // tf32 bits of in_proj_w[:E]
__device__ uint32_t g_Wk2_t[E_ * CS_];       // tf32 bits of Wk @ kv_w
__device__ uint32_t g_Wv2_t[E_ * CS_];       // tf32 bits of Wv @ kv_w
__device__ uint32_t g_Mw_t [CT_ * E_];       // tf32 bits of fuse_w @ out_proj_w
__device__ float    g_fb   [CT_];            // fuse_w @ out_proj_b
__device__ uint32_t g_Q  [B_ * NH_ * S_ * HD_]; // tf32 bits, [b][h][s][d]
__device__ uint32_t g_K  [B_ * NH_ * S_ * HD_];
__device__ __half   g_Vh [B_ * NH_ * HD_ * S_]; // fp16, TRANSPOSED [b][h][d][s]
__device__ float    g_ctx[B_ * S_ * E_];        // [b][s][e] fp32
__device__ float    g_linv[B_ * NH_ * S_];      // 1/l per (bh, q)
// fp16x2 unnormalized e, PERMUTED within each 16-word group: stored pos = 4*tig+nt
__device__ uint32_t g_Es[(size_t)B_ * NH_ * S_ * S_ / 2];

// ---------------- helpers ----------------
__device__ __forceinline__ uint32_t f2tf32(float x) {
    uint32_t r;
    asm("cvt.rna.tf32.f32 %0, %1;" : "=r"(r) : "f"(x));
    return r;
}
__device__ __forceinline__ void mma_tf32(float d[4], const uint32_t a[4],
                                         const uint32_t b[2], const float c[4]) {
    asm volatile(
        "mma.sync.aligned.m16n8k8.row.col.f32.tf32.tf32.f32 "
        "{%0,%1,%2,%3}, {%4,%5,%6,%7}, {%8,%9}, {%10,%11,%12,%13};"
        : "=f"(d[0]), "=f"(d[1]), "=f"(d[2]), "=f"(d[3])
        : "r"(a[0]), "r"(a[1]), "r"(a[2]), "r"(a[3]),
          "r"(b[0]), "r"(b[1]),
          "f"(c[0]), "f"(c[1]), "f"(c[2]), "f"(c[3]));
}
__device__ __forceinline__ void mma_f16(float d[4], const uint32_t a[4],
                                        const uint32_t b[2], const float c[4]) {
    asm volatile(
        "mma.sync.aligned.m16n8k16.row.col.f32.f16.f16.f32 "
        "{%0,%1,%2,%3}, {%4,%5,%6,%7}, {%8,%9}, {%10,%11,%12,%13};"
        : "=f"(d[0]), "=f"(d[1]), "=f"(d[2]), "=f"(d[3])
        : "r"(a[0]), "r"(a[1]), "r"(a[2]), "r"(a[3]),
          "r"(b[0]), "r"(b[1]),
          "f"(c[0]), "f"(c[1]), "f"(c[2]), "f"(c[3]));
}
__device__ __forceinline__ uint32_t pack_h2(float lo, float hi) {
    __half2 h = __floats2half2_rn(lo, hi);
    return *reinterpret_cast<uint32_t*>(&h);
}

// ---------------- kernel 0: fold weight chains -> tf32 bits, zero attn map ----------------
__global__ void k_combine(const float* __restrict__ in_proj_w,
                          const float* __restrict__ kv_w,
                          const float* __restrict__ fuse_w,
                          const float* __restrict__ out_proj_w,
                          const float* __restrict__ out_proj_b,
                          float* __restrict__ out_attn) {
    int idx = blockIdx.x * blockDim.x + threadIdx.x;
    const int N1 = E_ * CS_;          // 32768  Wk2
    const int N2 = 2 * N1;            // 65536  Wv2
    const int N3 = N2 + CT_ * E_;     // 131072 Mw
    const int N4 = N3 + CT_;          // 131328 fb
    const int N5 = N4 + E_ * E_;      // 196864 Wq bits
    const int N6 = N5 + B_ * S_;      // 205056 attn zero
    if (idx < N1) {
        int f = idx / CS_, c = idx % CS_;
        float s = 0.f;
        for (int e = 0; e < E_; e++)
            s += in_proj_w[(E_ + f) * E_ + e] * kv_w[e * CS_ + c];
        g_Wk2_t[idx] = f2tf32(s);
    } else if (idx < N2) {
        int j = idx - N1;
        int f = j / CS_, c = j % CS_;
        float s = 0.f;
        for (int e = 0; e < E_; e++)
            s += in_proj_w[(2 * E_ + f) * E_ + e] * kv_w[e * CS_ + c];
        g_Wv2_t[j] = f2tf32(s);
    } else if (idx < N3) {
        int j = idx - N2;
        int cc = j / E_, ep = j % E_;
        float s = 0.f;
        for (int e = 0; e < E_; e++)
            s += fuse_w[cc * E_ + e] * out_proj_w[e * E_ + ep];
        g_Mw_t[j] = f2tf32(s);
    } else if (idx < N4) {
        int cc = idx - N3;
        float s = 0.f;
        for (int e = 0; e < E_; e++)
            s += fuse_w[cc * E_ + e] * out_proj_b[e];
        g_fb[cc] = s;
    } else if (idx < N5) {
        int j = idx - N4;
        g_Wq_t[j] = f2tf32(in_proj_w[j]);
    } else if (idx < N6) {
        out_attn[idx - N5] = 0.f;
    }
}

// ---------------- kernel 1: Q/K/V projection, tf32 MMA (merged 3-way) ----------------
// blockIdx.z: which = z>>3 (0=Q,1=K,2=V), b = z&7
// Q,K stored as tf32 bits [bh][s][d]; V stored fp16 TRANSPOSED [bh][d][s].
__global__ void __launch_bounds__(256) k_proj(const float* __restrict__ tgt,
                                              const float* __restrict__ src,
                                              const float* __restrict__ in_proj_b) {
    __shared__ uint32_t As[32 * 68];   // [c][s] tf32 bits
    __shared__ uint32_t Bs[64 * 36];   // [e][c] tf32 bits
    int which = blockIdx.z >> 3;
    int b = blockIdx.z & 7;
    const uint32_t* W = (which == 0) ? g_Wq_t : (which == 1 ? g_Wk2_t : g_Wv2_t);
    const float* In = (which == 0) ? tgt : src;
    const float* bias = in_proj_b + which * E_;
    int Cin = (which == 0) ? CT_ : CS_;

    int s0 = blockIdx.x * 64, e0 = blockIdx.y * 64;
    int tid = threadIdx.x;
    int lane = tid & 31, w = tid >> 5;
    int gid = lane >> 2, tig = lane & 3;
    int mw = w >> 1, nh = w & 1;   // s block of 16, e half of 32
    const float* Ab = In + (size_t)b * Cin * S_;

    int sl = tid & 63, cl0 = tid >> 6;    // A loader coords
    int clB = tid & 31, el0 = tid >> 5;   // B loader coords

    float acc[4][4] = {};
    int nchunks = Cin >> 5;
    for (int ch = 0; ch < nchunks; ch++) {
        int c0 = ch << 5;
        __syncthreads();
        #pragma unroll
        for (int r = 0; r < 8; r++) {
            int cl = cl0 + 4 * r;
            As[cl * 68 + sl] = f2tf32(Ab[(size_t)(c0 + cl) * S_ + s0 + sl]);
        }
        #pragma unroll
        for (int r = 0; r < 8; r++) {
            int el = el0 + 8 * r;
            Bs[el * 36 + clB] = W[(size_t)(e0 + el) * Cin + c0 + clB];
        }
        __syncthreads();
        #pragma unroll
        for (int ks = 0; ks < 4; ks++) {
            uint32_t a[4];
            int sr = 16 * mw + gid;
            int cc = 8 * ks + tig;
            a[0] = As[cc * 68 + sr];
            a[1] = As[cc * 68 + sr + 8];
            a[2] = As[(cc + 4) * 68 + sr];
            a[3] = As[(cc + 4) * 68 + sr + 8];
            #pragma unroll
            for (int nt = 0; nt < 4; nt++) {
                uint32_t bb[2];
                int er = 32 * nh + 8 * nt + gid;
                bb[0] = Bs[er * 36 + 8 * ks + tig];
                bb[1] = Bs[er * 36 + 8 * ks + tig + 4];
                mma_tf32(acc[nt], a, bb, acc[nt]);
            }
        }
    }
    // epilogue
    if (which != 2) {
        uint32_t* Out = (which == 0) ? g_Q : g_K;
        #pragma unroll
        for (int nt = 0; nt < 4; nt++) {
            int e = e0 + 32 * nh + 8 * nt + 2 * tig;
            float b0 = bias[e], b1 = bias[e + 1];
            int h = e >> 5, d = e & 31;
            int s = s0 + 16 * mw + gid;
            uint32_t lo, hi;
            size_t base = (((size_t)(b * NH_ + h) * S_ + s) << 5) + d;
            lo = f2tf32(acc[nt][0] + b0); hi = f2tf32(acc[nt][1] + b1);
            *reinterpret_cast<uint2*>(&Out[base]) = make_uint2(lo, hi);
            lo = f2tf32(acc[nt][2] + b0); hi = f2tf32(acc[nt][3] + b1);
            *reinterpret_cast<uint2*>(&Out[base + (8u << 5)]) = make_uint2(lo, hi);
        }
    } else {
        // V: fp16 transposed [bh][d][s]
        #pragma unroll
        for (int nt = 0; nt < 4; nt++) {
            int e = e0 + 32 * nh + 8 * nt + 2 * tig;
            float b0 = bias[e], b1 = bias[e + 1];
            int h = e >> 5, d = e & 31;
            int s = s0 + 16 * mw + gid;
            size_t r0 = ((size_t)(b * NH_ + h) * HD_ + d) * S_;
            size_t r1 = r0 + S_;   // d+1 row (same head: d = 8nt+2tig <= 30)
            g_Vh[r0 + s]     = __float2half(acc[nt][0] + b0);
            g_Vh[r1 + s]     = __float2half(acc[nt][1] + b1);
            g_Vh[r0 + s + 8] = __float2half(acc[nt][2] + b0);
            g_Vh[r1 + s + 8] = __float2half(acc[nt][3] + b1);
        }
    }
}

// ---------------- kernel 2: fused attention, single pass, register P ----------------
// S = QK^T in tf32 MMA; exp in regs; P packed fp16x2 feeds m16n8k16 O-MMA directly.
// Unnormalized e streamed to g_Es via ONE uint4 STG.128 per row-half (permuted layout:
// within each 16-word group, stored position = 4*tig + nt for keypair word 4*nt + tig).
// smem words: Qs[64*36]@0, Ks[64*36]@2304, Vs[32*36]@4608, lsum@5760, linv@5824, redO@5888[2048]
// total 7936 words = 31744 B
__global__ void __launch_bounds__(256, 2) k_attn() {
    extern __shared__ uint32_t sm[];
    uint32_t* Qs = sm;
    uint32_t* Ks = sm + 2304;
    uint32_t* Vs = sm + 4608;           // [d][key-pair words], stride 36
    float* lsum  = (float*)(sm + 5760);
    float* linv  = (float*)(sm + 5824);
    float* redO  = (float*)(sm + 5888); // [mw][nj][16][8]

    int bh = blockIdx.y;
    int b = bh >> 3, h = bh & 7;
    int q0 = blockIdx.x * 64;
    const uint32_t* Qb = g_Q + (size_t)bh * S_ * HD_;
    const uint32_t* Kb = g_K + (size_t)bh * S_ * HD_;
    const uint32_t* VhW = reinterpret_cast<const uint32_t*>(g_Vh) + (size_t)bh * HD_ * (S_ / 2);
    uint32_t* EsW = g_Es + ((size_t)bh * S_ * S_ / 2);

    int tid = threadIdx.x;
    int lane = tid & 31, w = tid >> 5;
    int gid = lane >> 2, tig = lane & 3;
    int r8 = tid >> 5, d32 = tid & 31;      // K loader coords
    int vd = tid >> 3, vw0 = tid & 7;       // V loader coords

    int mw = w >> 1, nh = w & 1;

    if (tid < 64) lsum[tid] = 0.f;

    #pragma unroll
    for (int r = 0; r < 8; r++) {
        int q = r8 + 8 * r;
        Qs[q * 36 + d32] = Qb[(size_t)(q0 + q) * HD_ + d32];
    }
    __syncthreads();

    // Q fragments, register-resident
    uint32_t aq[4][4];
    #pragma unroll
    for (int ks = 0; ks < 4; ks++) {
        int qr = 16 * mw + gid;
        int c  = ks * 8 + tig;
        aq[ks][0] = Qs[qr * 36 + c];
        aq[ks][1] = Qs[(qr + 8) * 36 + c];
        aq[ks][2] = Qs[qr * 36 + c + 4];
        aq[ks][3] = Qs[(qr + 8) * 36 + c + 4];
    }

    const float scale = 0.17677669529663687f; // 1/sqrt(32)
    float l0 = 0.f, l1 = 0.f;
    float oacc[4][4] = {};   // [nj: d 8-col tile][frag]

    // prefetch tile 0
    uint32_t kreg[8], vreg[4];
    #pragma unroll
    for (int r = 0; r < 8; r++)
        kreg[r] = Kb[(size_t)(r8 + 8 * r) * HD_ + d32];
    #pragma unroll
    for (int r = 0; r < 4; r++)
        vreg[r] = VhW[(size_t)vd * (S_ / 2) + vw0 + 8 * r];

    for (int t = 0; t < 16; t++) {
        int k0 = t * 64;
        __syncthreads();   // prior tile compute done with Ks/Vs
        #pragma unroll
        for (int r = 0; r < 8; r++)
            Ks[(r8 + 8 * r) * 36 + d32] = kreg[r];
        #pragma unroll
        for (int r = 0; r < 4; r++)
            Vs[vd * 36 + vw0 + 8 * r] = vreg[r];
        __syncthreads();
        if (t < 15) {
            int k0n = k0 + 64;
            #pragma unroll
            for (int r = 0; r < 8; r++)
                kreg[r] = Kb[(size_t)(k0n + r8 + 8 * r) * HD_ + d32];
            #pragma unroll
            for (int r = 0; r < 4; r++)
                vreg[r] = VhW[(size_t)vd * (S_ / 2) + (k0n >> 1) + vw0 + 8 * r];
        }

        // ---- S phase: tf32 MMA over this warp's 32-key half
        float sacc[4][4] = {};
        #pragma unroll
        for (int ks = 0; ks < 4; ks++) {
            #pragma unroll
            for (int nt = 0; nt < 4; nt++) {
                uint32_t bf[2];
                int key = 32 * nh + 8 * nt + gid;
                int d0  = ks * 8 + tig;
                bf[0] = Ks[key * 36 + d0];
                bf[1] = Ks[key * 36 + d0 + 4];
                mma_tf32(sacc[nt], aq[ks], bf, sacc[nt]);
            }
        }

        // ---- exp + pack + row-sum partials
        uint32_t pl[4], ph[4];
        int qr = 16 * mw + gid;
        #pragma unroll
        for (int nt = 0; nt < 4; nt++) {
            float e0 = __expf(sacc[nt][0] * scale);
            float e1 = __expf(sacc[nt][1] * scale);
            float e2 = __expf(sacc[nt][2] * scale);
            float e3 = __expf(sacc[nt][3] * scale);
            l0 += e0 + e1;
            l1 += e2 + e3;
            pl[nt] = pack_h2(e0, e1);
            ph[nt] = pack_h2(e2, e3);
        }
        // stream to gmem: permuted layout -> one STG.128 per row-half
        {
            size_t esb = ((size_t)(q0 + qr)) * (S_ / 2) + (k0 >> 1) + 16 * nh + 4 * tig;
            __stcs(reinterpret_cast<uint4*>(&EsW[esb]),
                   make_uint4(pl[0], pl[1], pl[2], pl[3]));
            __stcs(reinterpret_cast<uint4*>(&EsW[esb + 8 * (S_ / 2)]),
                   make_uint4(ph[0], ph[1], ph[2], ph[3]));
        }

        // ---- O phase: fp16 m16n8k16, A = packed P frags (no smem roundtrip)
        #pragma unroll
        for (int c = 0; c < 2; c++) {
            uint32_t ap[4] = { pl[2 * c], ph[2 * c], pl[2 * c + 1], ph[2 * c + 1] };
            int kwb = 16 * nh + 8 * c;   // key word base within tile
            #pragma unroll
            for (int nj = 0; nj < 4; nj++) {
                uint32_t bv[2];
                int drow = 8 * nj + gid;
                bv[0] = Vs[drow * 36 + kwb + tig];
                bv[1] = Vs[drow * 36 + kwb + tig + 4];
                mma_f16(oacc[nj], ap, bv, oacc[nj]);
            }
        }
    }

    // ---- reduce row sums; linv to smem + gmem
    __syncthreads();
    atomicAdd(&lsum[16 * mw + gid], l0);
    atomicAdd(&lsum[16 * mw + gid + 8], l1);
    __syncthreads();
    if (tid < 64) {
        float li = 1.0f / lsum[tid];
        linv[tid] = li;
        g_linv[(size_t)bh * S_ + q0 + tid] = li;
    }
    __syncthreads();

    // ---- combine nh warp pairs, normalize, write ctx
    if (nh == 1) {
        #pragma unroll
        for (int nj = 0; nj < 4; nj++) {
            float* rb = &redO[((mw * 4 + nj) * 16) * 8];
            rb[gid * 8 + 2 * tig]           = oacc[nj][0];
            rb[gid * 8 + 2 * tig + 1]       = oacc[nj][1];
            rb[(gid + 8) * 8 + 2 * tig]     = oacc[nj][2];
            rb[(gid + 8) * 8 + 2 * tig + 1] = oacc[nj][3];
        }
    }
    __syncthreads();
    if (nh == 0) {
        int qr = 16 * mw + gid;
        float li0 = linv[qr], li1 = linv[qr + 8];
        #pragma unroll
        for (int nj = 0; nj < 4; nj++) {
            const float* rb = &redO[((mw * 4 + nj) * 16) * 8];
            float o0 = (oacc[nj][0] + rb[gid * 8 + 2 * tig]) * li0;
            float o1 = (oacc[nj][1] + rb[gid * 8 + 2 * tig + 1]) * li0;
            float o2 = (oacc[nj][2] + rb[(gid + 8) * 8 + 2 * tig]) * li1;
            float o3 = (oacc[nj][3] + rb[(gid + 8) * 8 + 2 * tig + 1]) * li1;
            int d = h * HD_ + 8 * nj + 2 * tig;
            *reinterpret_cast<float2*>(
                &g_ctx[((size_t)b * S_ + q0 + qr) * E_ + d]) = make_float2(o0, o1);
            *reinterpret_cast<float2*>(
                &g_ctx[((size_t)b * S_ + q0 + qr + 8) * E_ + d]) = make_float2(o2, o3);
        }
    }
}

// ---------------- kernel 3: attn map column sums from streamed e ----------------
// out_attn[b][k] = (1/8192) * sum_{h,q} e[bh][q][k] * linv[bh][q]
// grid (8, 32), block 256: thread owns one uint4 column (4 stored words) over 128 rows.
// Permuted layout inversion: stored word W -> keypair (W & ~15) + 4*(W&3) + ((W>>2)&3).
// For a thread's uint4 at word base 4*col: j-th element -> keypair kp0 + 4*j,
// kp0 = (col>>2)*16 + (col&3).
__global__ void __launch_bounds__(256) k_amap(float* __restrict__ out_attn) {
    int b = blockIdx.x;
    int rc = blockIdx.y;                 // 32 chunks of 256 rows
    int col = threadIdx.x & 127;         // uint4 column (0..127)
    int rh = threadIdx.x >> 7;           // row half (0/1)
    const uint4* Eb = reinterpret_cast<const uint4*>(
        g_Es + ((size_t)b * NH_ * S_) * (S_ / 2));
    const float* Lb = g_linv + (size_t)b * NH_ * S_;
    int row0 = rc * 256 + rh * 128;
    float a0 = 0.f, a1 = 0.f, a2 = 0.f, a3 = 0.f;
    float b0 = 0.f, b1 = 0.f, b2 = 0.f, b3 = 0.f;
    #pragma unroll 8
    for (int i = 0; i < 128; i++) {
        int rr = row0 + i;
        float li = Lb[rr];
        uint4 u = __ldcs(&Eb[(size_t)rr * 128 + col]);
        float2 f0 = __half22float2(*reinterpret_cast<__half2*>(&u.x));
        float2 f1 = __half22float2(*reinterpret_cast<__half2*>(&u.y));
        float2 f2 = __half22float2(*reinterpret_cast<__half2*>(&u.z));
        float2 f3 = __half22float2(*reinterpret_cast<__half2*>(&u.w));
        a0 = fmaf(f0.x, li, a0); b0 = fmaf(f0.y, li, b0);
        a1 = fmaf(f1.x, li, a1); b1 = fmaf(f1.y, li, b1);
        a2 = fmaf(f2.x, li, a2); b2 = fmaf(f2.y, li, b2);
        a3 = fmaf(f3.x, li, a3); b3 = fmaf(f3.y, li, b3);
    }
    int kp0 = ((col >> 2) << 4) + (col & 3);
    const float sc = 1.0f / 8192.0f;
    float* oa = out_attn + b * S_;
    atomicAdd(&oa[2 * (kp0 + 0)],      a0 * sc);
    atomicAdd(&oa[2 * (kp0 + 0) + 1],  b0 * sc);
    atomicAdd(&oa[2 * (kp0 + 4)],      a1 * sc);
    atomicAdd(&oa[2 * (kp0 + 4) + 1],  b1 * sc);
    atomicAdd(&oa[2 * (kp0 + 8)],      a2 * sc);
    atomicAdd(&oa[2 * (kp0 + 8) + 1],  b2 * sc);
    atomicAdd(&oa[2 * (kp0 + 12)],     a3 * sc);
    atomicAdd(&oa[2 * (kp0 + 12) + 1], b3 * sc);
}

// ---------------- kernel 4: fuse + BN + SiLU + residual, tf32 MMA ----------------
__global__ void __launch_bounds__(256) k_fuse(const float* __restrict__ tgt,
                       const float* __restrict__ gamma,
                       const float* __restrict__ beta,
                       const float* __restrict__ mean,
                       const float* __restrict__ var,
                       float* __restrict__ out) {
    __shared__ uint32_t As[64 * 36];  // Mw bits [c][e-chunk]
    __shared__ uint32_t Bs[64 * 36];  // ctx bits [s][e-chunk]
    int b = blockIdx.z;
    int c0 = blockIdx.x * 64, s0 = blockIdx.y * 64;
    const float* Cb = g_ctx + (size_t)b * S_ * E_;
    int tid = threadIdx.x;
    int lane = tid & 31, w = tid >> 5;
    int gid = lane >> 2, tig = lane & 3;
    int mw = w >> 1, nh = w & 1;
    int el = tid & 31, rl0 = tid >> 5;

    float acc[4][4] = {};
    #pragma unroll 1
    for (int ch = 0; ch < 8; ch++) {
        int e0 = ch << 5;
        __syncthreads();
        #pragma unroll
        for (int r = 0; r < 8; r++) {
            int row = rl0 + 8 * r;
            As[row * 36 + el] = g_Mw_t[(size_t)(c0 + row) * E_ + e0 + el];
            Bs[row * 36 + el] = f2tf32(Cb[(size_t)(s0 + row) * E_ + e0 + el]);
        }
        __syncthreads();
        #pragma unroll
        for (int ks = 0; ks < 4; ks++) {
            uint32_t a[4];
            int cr = 16 * mw + gid;
            int ec = 8 * ks + tig;
            a[0] = As[cr * 36 + ec];
            a[1] = As[(cr + 8) * 36 + ec];
            a[2] = As[cr * 36 + ec + 4];
            a[3] = As[(cr + 8) * 36 + ec + 4];
            #pragma unroll
            for (int nt = 0; nt < 4; nt++) {
                uint32_t bb[2];
                int sr = 32 * nh + 8 * nt + gid;
                bb[0] = Bs[sr * 36 + ec];
                bb[1] = Bs[sr * 36 + ec + 4];
                mma_tf32(acc[nt], a, bb, acc[nt]);
            }
        }
    }
    int c = c0 + 16 * mw + gid;
    float inv0 = gamma[c] * rsqrtf(var[c] + 1e-5f);
    float mu0 = mean[c], bet0 = beta[c], fb0 = g_fb[c];
    float inv1 = gamma[c + 8] * rsqrtf(var[c + 8] + 1e-5f);
    float mu1 = mean[c + 8], bet1 = beta[c + 8], fb1 = g_fb[c + 8];
    #pragma unroll
    for (int nt = 0; nt < 4; nt++) {
        int s = s0 + 32 * nh + 8 * nt + 2 * tig;
        size_t off0 = (size_t)b * (CT_ * S_) + (size_t)c * S_ + s;
        size_t off1 = off0 + (size_t)8 * S_;
        float2 t0 = *reinterpret_cast<const float2*>(&tgt[off0]);
        float2 t1 = *reinterpret_cast<const float2*>(&tgt[off1]);
        float bn, sg;
        float2 y0, y1;
        bn = (acc[nt][0] + fb0 - mu0) * inv0 + bet0;
        sg = 1.0f / (1.0f + __expf(-bn)); y0.x = t0.x + bn * sg;
        bn = (acc[nt][1] + fb0 - mu0) * inv0 + bet0;
        sg = 1.0f / (1.0f + __expf(-bn)); y0.y = t0.y + bn * sg;
        bn = (acc[nt][2] + fb1 - mu1) * inv1 + bet1;
        sg = 1.0f / (1.0f + __expf(-bn)); y1.x = t1.x + bn * sg;
        bn = (acc[nt][3] + fb1 - mu1) * inv1 + bet1;
        sg = 1.0f / (1.0f + __expf(-bn)); y1.y = t1.y + bn * sg;
        *reinterpret_cast<float2*>(&out[off0]) = y0;
        *reinterpret_cast<float2*>(&out[off1]) = y1;
    }
}

// ---------------- host launch ----------------
extern "C" void kernel_launch(void* const* d_in, const int* in_sizes, int n_in,
                              void* d_out, int out_size) {
    const float* tgt        = (const float*)d_in[0];
    const float* src        = (const float*)d_in[1];
    const float* kv_w       = (const float*)d_in[2];
    const float* in_proj_w  = (const float*)d_in[3];
    const float* in_proj_b  = (const float*)d_in[4];
    const float* out_proj_w = (const float*)d_in[5];
    const float* out_proj_b = (const float*)d_in[6];
    const float* fuse_w     = (const float*)d_in[7];
    const float* bn_gamma   = (const float*)d_in[8];
    const float* bn_beta    = (const float*)d_in[9];
    const float* bn_mean    = (const float*)d_in[10];
    const float* bn_var     = (const float*)d_in[11];

    float* out_y    = (float*)d_out;                         // B*Ct*H*W
    float* out_attn = (float*)d_out + (size_t)B_ * CT_ * S_; // B*H*W

    static const int ATTN_SMEM = 31744;

    // 0. fold weights -> tf32 bit matrices, zero attn map
    k_combine<<<(205056 + 255) / 256, 256>>>(in_proj_w, kv_w, fuse_w,
                                             out_proj_w, out_proj_b, out_attn);

    // 1. Q/K/V projections in one launch (tf32 MMA)
    dim3 gp(S_ / 64, E_ / 64, 3 * B_);
    k_proj<<<gp, 256>>>(tgt, src, in_proj_b);

    // 2. fused single-pass tensor-core attention (streams e + linv to gmem)
    dim3 ga(S_ / 64, B_ * NH_);
    k_attn<<<ga, 256, ATTN_SMEM>>>();

    // 3. attn map column sums (bandwidth-optimized)
    dim3 gm(B_, 32);
    k_amap<<<gm, 256>>>(out_attn);

    // 4. fuse + BN + SiLU + residual (tf32 MMA)
    dim3 gf(CT_ / 64, S_ / 64, B_);
    k_fuse<<<gf, 256>>>(tgt, bn_gamma, bn_beta, bn_mean, bn_var, out_y);
}

// round 14
// speedup vs baseline: 1.3439x; 1.1115x over previous
#include <cuda_runtime.h>
#include <cuda_fp16.h>
#include <cstdint>
#include <math.h>

// Problem constants
#define B_   8
#define S_   1024      // H*W
#define E_   256
#define CS_  128
#define CT_  256
#define NH_  8
#define HD_  32

// ---------------- scratch (static device memory; no allocations) ----------------
__device__ uint32_t g_Wq_t [E_ * E_];        // tf32 bits of in_proj_w[:E]
__device__ uint32_t g_Wk2_t[E_ * CS_];       // tf32 bits of Wk @ kv_w
__device__ uint32_t g_Wv2_t[E_ * CS_];       // tf32 bits of Wv @ kv_w
__device__ uint32_t g_Mw_t [CT_ * E_];       // tf32 bits of fuse_w @ out_proj_w
__device__ float    g_fb   [CT_];            // fuse_w @ out_proj_b
__device__ uint32_t g_Q  [B_ * NH_ * S_ * HD_]; // tf32 bits, [b][h][s][d]
__device__ uint32_t g_K  [B_ * NH_ * S_ * HD_];
__device__ __half   g_Vh [B_ * NH_ * HD_ * S_]; // fp16, TRANSPOSED [b][h][d][s]
__device__ float    g_ctx[B_ * S_ * E_];        // [b][s][e] fp32
__device__ float    g_linv[B_ * NH_ * S_];      // 1/l per (bh, q)
// fp16x2 unnormalized e, PERMUTED within each 16-word group: stored pos = 4*tig+nt
__device__ uint32_t g_Es[(size_t)B_ * NH_ * S_ * S_ / 2];

// ---------------- helpers ----------------
__device__ __forceinline__ uint32_t f2tf32(float x) {
    uint32_t r;
    asm("cvt.rna.tf32.f32 %0, %1;" : "=r"(r) : "f"(x));
    return r;
}
__device__ __forceinline__ void mma_tf32(float d[4], const uint32_t a[4],
                                         const uint32_t b[2], const float c[4]) {
    asm volatile(
        "mma.sync.aligned.m16n8k8.row.col.f32.tf32.tf32.f32 "
        "{%0,%1,%2,%3}, {%4,%5,%6,%7}, {%8,%9}, {%10,%11,%12,%13};"
        : "=f"(d[0]), "=f"(d[1]), "=f"(d[2]), "=f"(d[3])
        : "r"(a[0]), "r"(a[1]), "r"(a[2]), "r"(a[3]),
          "r"(b[0]), "r"(b[1]),
          "f"(c[0]), "f"(c[1]), "f"(c[2]), "f"(c[3]));
}
__device__ __forceinline__ void mma_f16(float d[4], const uint32_t a[4],
                                        const uint32_t b[2], const float c[4]) {
    asm volatile(
        "mma.sync.aligned.m16n8k16.row.col.f32.f16.f16.f32 "
        "{%0,%1,%2,%3}, {%4,%5,%6,%7}, {%8,%9}, {%10,%11,%12,%13};"
        : "=f"(d[0]), "=f"(d[1]), "=f"(d[2]), "=f"(d[3])
        : "r"(a[0]), "r"(a[1]), "r"(a[2]), "r"(a[3]),
          "r"(b[0]), "r"(b[1]),
          "f"(c[0]), "f"(c[1]), "f"(c[2]), "f"(c[3]));
}
__device__ __forceinline__ uint32_t pack_h2(float lo, float hi) {
    __half2 h = __floats2half2_rn(lo, hi);
    return *reinterpret_cast<uint32_t*>(&h);
}

// ---------------- kernel 0: fold weight chains -> tf32 bits, zero attn map ----------------
__global__ void k_combine(const float* __restrict__ in_proj_w,
                          const float* __restrict__ kv_w,
                          const float* __restrict__ fuse_w,
                          const float* __restrict__ out_proj_w,
                          const float* __restrict__ out_proj_b,
                          float* __restrict__ out_attn) {
    int idx = blockIdx.x * blockDim.x + threadIdx.x;
    const int N1 = E_ * CS_;          // 32768  Wk2
    const int N2 = 2 * N1;            // 65536  Wv2
    const int N3 = N2 + CT_ * E_;     // 131072 Mw
    const int N4 = N3 + CT_;          // 131328 fb
    const int N5 = N4 + E_ * E_;      // 196864 Wq bits
    const int N6 = N5 + B_ * S_;      // 205056 attn zero
    if (idx < N1) {
        int f = idx / CS_, c = idx % CS_;
        float s = 0.f;
        for (int e = 0; e < E_; e++)
            s += in_proj_w[(E_ + f) * E_ + e] * kv_w[e * CS_ + c];
        g_Wk2_t[idx] = f2tf32(s);
    } else if (idx < N2) {
        int j = idx - N1;
        int f = j / CS_, c = j % CS_;
        float s = 0.f;
        for (int e = 0; e < E_; e++)
            s += in_proj_w[(2 * E_ + f) * E_ + e] * kv_w[e * CS_ + c];
        g_Wv2_t[j] = f2tf32(s);
    } else if (idx < N3) {
        int j = idx - N2;
        int cc = j / E_, ep = j % E_;
        float s = 0.f;
        for (int e = 0; e < E_; e++)
            s += fuse_w[cc * E_ + e] * out_proj_w[e * E_ + ep];
        g_Mw_t[j] = f2tf32(s);
    } else if (idx < N4) {
        int cc = idx - N3;
        float s = 0.f;
        for (int e = 0; e < E_; e++)
            s += fuse_w[cc * E_ + e] * out_proj_b[e];
        g_fb[cc] = s;
    } else if (idx < N5) {
        int j = idx - N4;
        g_Wq_t[j] = f2tf32(in_proj_w[j]);
    } else if (idx < N6) {
        out_attn[idx - N5] = 0.f;
    }
}

// ---------------- kernel 1: Q/K/V projection, tf32 MMA (merged 3-way) ----------------
// blockIdx.z: which = z>>3 (0=Q,1=K,2=V), b = z&7
// Q,K stored as tf32 bits [bh][s][d]; V stored fp16 TRANSPOSED [bh][d][s].
__global__ void __launch_bounds__(256) k_proj(const float* __restrict__ tgt,
                                              const float* __restrict__ src,
                                              const float* __restrict__ in_proj_b) {
    __shared__ uint32_t As[32 * 68];   // [c][s] tf32 bits
    __shared__ uint32_t Bs[64 * 36];   // [e][c] tf32 bits
    int which = blockIdx.z >> 3;
    int b = blockIdx.z & 7;
    const uint32_t* W = (which == 0) ? g_Wq_t : (which == 1 ? g_Wk2_t : g_Wv2_t);
    const float* In = (which == 0) ? tgt : src;
    const float* bias = in_proj_b + which * E_;
    int Cin = (which == 0) ? CT_ : CS_;

    int s0 = blockIdx.x * 64, e0 = blockIdx.y * 64;
    int tid = threadIdx.x;
    int lane = tid & 31, w = tid >> 5;
    int gid = lane >> 2, tig = lane & 3;
    int mw = w >> 1, nh = w & 1;   // s block of 16, e half of 32
    const float* Ab = In + (size_t)b * Cin * S_;

    int sl = tid & 63, cl0 = tid >> 6;    // A loader coords
    int clB = tid & 31, el0 = tid >> 5;   // B loader coords

    float acc[4][4] = {};
    int nchunks = Cin >> 5;
    for (int ch = 0; ch < nchunks; ch++) {
        int c0 = ch << 5;
        __syncthreads();
        #pragma unroll
        for (int r = 0; r < 8; r++) {
            int cl = cl0 + 4 * r;
            As[cl * 68 + sl] = f2tf32(Ab[(size_t)(c0 + cl) * S_ + s0 + sl]);
        }
        #pragma unroll
        for (int r = 0; r < 8; r++) {
            int el = el0 + 8 * r;
            Bs[el * 36 + clB] = W[(size_t)(e0 + el) * Cin + c0 + clB];
        }
        __syncthreads();
        #pragma unroll
        for (int ks = 0; ks < 4; ks++) {
            uint32_t a[4];
            int sr = 16 * mw + gid;
            int cc = 8 * ks + tig;
            a[0] = As[cc * 68 + sr];
            a[1] = As[cc * 68 + sr + 8];
            a[2] = As[(cc + 4) * 68 + sr];
            a[3] = As[(cc + 4) * 68 + sr + 8];
            #pragma unroll
            for (int nt = 0; nt < 4; nt++) {
                uint32_t bb[2];
                int er = 32 * nh + 8 * nt + gid;
                bb[0] = Bs[er * 36 + 8 * ks + tig];
                bb[1] = Bs[er * 36 + 8 * ks + tig + 4];
                mma_tf32(acc[nt], a, bb, acc[nt]);
            }
        }
    }
    // epilogue
    if (which != 2) {
        uint32_t* Out = (which == 0) ? g_Q : g_K;
        #pragma unroll
        for (int nt = 0; nt < 4; nt++) {
            int e = e0 + 32 * nh + 8 * nt + 2 * tig;
            float b0 = bias[e], b1 = bias[e + 1];
            int h = e >> 5, d = e & 31;
            int s = s0 + 16 * mw + gid;
            uint32_t lo, hi;
            size_t base = (((size_t)(b * NH_ + h) * S_ + s) << 5) + d;
            lo = f2tf32(acc[nt][0] + b0); hi = f2tf32(acc[nt][1] + b1);
            *reinterpret_cast<uint2*>(&Out[base]) = make_uint2(lo, hi);
            lo = f2tf32(acc[nt][2] + b0); hi = f2tf32(acc[nt][3] + b1);
            *reinterpret_cast<uint2*>(&Out[base + (8u << 5)]) = make_uint2(lo, hi);
        }
    } else {
        // V: fp16 transposed [bh][d][s]
        #pragma unroll
        for (int nt = 0; nt < 4; nt++) {
            int e = e0 + 32 * nh + 8 * nt + 2 * tig;
            float b0 = bias[e], b1 = bias[e + 1];
            int h = e >> 5, d = e & 31;
            int s = s0 + 16 * mw + gid;
            size_t r0 = ((size_t)(b * NH_ + h) * HD_ + d) * S_;
            size_t r1 = r0 + S_;   // d+1 row (same head: d = 8nt+2tig <= 30)
            g_Vh[r0 + s]     = __float2half(acc[nt][0] + b0);
            g_Vh[r1 + s]     = __float2half(acc[nt][1] + b1);
            g_Vh[r0 + s + 8] = __float2half(acc[nt][2] + b0);
            g_Vh[r1 + s + 8] = __float2half(acc[nt][3] + b1);
        }
    }
}

// ---------------- kernel 2: fused attention, single pass, register P ----------------
// S = QK^T in tf32 MMA; exp in regs; P packed fp16x2 feeds m16n8k16 O-MMA directly.
// Unnormalized e streamed to g_Es via ONE uint4 STG.128 per row-half (permuted layout:
// within each 16-word group, stored position = 4*tig + nt for keypair word 4*nt + tig).
// smem words: Qs[64*36]@0, Ks[64*36]@2304, Vs[32*36]@4608, lsum@5760, linv@5824, redO@5888[2048]
// total 7936 words = 31744 B
__global__ void __launch_bounds__(256, 2) k_attn() {
    extern __shared__ uint32_t sm[];
    uint32_t* Qs = sm;
    uint32_t* Ks = sm + 2304;
    uint32_t* Vs = sm + 4608;           // [d][key-pair words], stride 36
    float* lsum  = (float*)(sm + 5760);
    float* linv  = (float*)(sm + 5824);
    float* redO  = (float*)(sm + 5888); // [mw][nj][16][8]

    int bh = blockIdx.y;
    int b = bh >> 3, h = bh & 7;
    int q0 = blockIdx.x * 64;
    const uint32_t* Qb = g_Q + (size_t)bh * S_ * HD_;
    const uint32_t* Kb = g_K + (size_t)bh * S_ * HD_;
    const uint32_t* VhW = reinterpret_cast<const uint32_t*>(g_Vh) + (size_t)bh * HD_ * (S_ / 2);
    uint32_t* EsW = g_Es + ((size_t)bh * S_ * S_ / 2);

    int tid = threadIdx.x;
    int lane = tid & 31, w = tid >> 5;
    int gid = lane >> 2, tig = lane & 3;
    int r8 = tid >> 5, d32 = tid & 31;      // K loader coords
    int vd = tid >> 3, vw0 = tid & 7;       // V loader coords

    int mw = w >> 1, nh = w & 1;

    if (tid < 64) lsum[tid] = 0.f;

    #pragma unroll
    for (int r = 0; r < 8; r++) {
        int q = r8 + 8 * r;
        Qs[q * 36 + d32] = Qb[(size_t)(q0 + q) * HD_ + d32];
    }
    __syncthreads();

    // Q fragments, register-resident
    uint32_t aq[4][4];
    #pragma unroll
    for (int ks = 0; ks < 4; ks++) {
        int qr = 16 * mw + gid;
        int c  = ks * 8 + tig;
        aq[ks][0] = Qs[qr * 36 + c];
        aq[ks][1] = Qs[(qr + 8) * 36 + c];
        aq[ks][2] = Qs[qr * 36 + c + 4];
        aq[ks][3] = Qs[(qr + 8) * 36 + c + 4];
    }

    const float scale = 0.17677669529663687f; // 1/sqrt(32)
    float l0 = 0.f, l1 = 0.f;
    float oacc[4][4] = {};   // [nj: d 8-col tile][frag]

    // prefetch tile 0
    uint32_t kreg[8], vreg[4];
    #pragma unroll
    for (int r = 0; r < 8; r++)
        kreg[r] = Kb[(size_t)(r8 + 8 * r) * HD_ + d32];
    #pragma unroll
    for (int r = 0; r < 4; r++)
        vreg[r] = VhW[(size_t)vd * (S_ / 2) + vw0 + 8 * r];

    for (int t = 0; t < 16; t++) {
        int k0 = t * 64;
        __syncthreads();   // prior tile compute done with Ks/Vs
        #pragma unroll
        for (int r = 0; r < 8; r++)
            Ks[(r8 + 8 * r) * 36 + d32] = kreg[r];
        #pragma unroll
        for (int r = 0; r < 4; r++)
            Vs[vd * 36 + vw0 + 8 * r] = vreg[r];
        __syncthreads();
        if (t < 15) {
            int k0n = k0 + 64;
            #pragma unroll
            for (int r = 0; r < 8; r++)
                kreg[r] = Kb[(size_t)(k0n + r8 + 8 * r) * HD_ + d32];
            #pragma unroll
            for (int r = 0; r < 4; r++)
                vreg[r] = VhW[(size_t)vd * (S_ / 2) + (k0n >> 1) + vw0 + 8 * r];
        }

        // ---- S phase: tf32 MMA over this warp's 32-key half
        float sacc[4][4] = {};
        #pragma unroll
        for (int ks = 0; ks < 4; ks++) {
            #pragma unroll
            for (int nt = 0; nt < 4; nt++) {
                uint32_t bf[2];
                int key = 32 * nh + 8 * nt + gid;
                int d0  = ks * 8 + tig;
                bf[0] = Ks[key * 36 + d0];
                bf[1] = Ks[key * 36 + d0 + 4];
                mma_tf32(sacc[nt], aq[ks], bf, sacc[nt]);
            }
        }

        // ---- exp + pack + row-sum partials
        uint32_t pl[4], ph[4];
        int qr = 16 * mw + gid;
        #pragma unroll
        for (int nt = 0; nt < 4; nt++) {
            float e0 = __expf(sacc[nt][0] * scale);
            float e1 = __expf(sacc[nt][1] * scale);
            float e2 = __expf(sacc[nt][2] * scale);
            float e3 = __expf(sacc[nt][3] * scale);
            l0 += e0 + e1;
            l1 += e2 + e3;
            pl[nt] = pack_h2(e0, e1);
            ph[nt] = pack_h2(e2, e3);
        }
        // stream to gmem: permuted layout -> one STG.128 per row-half
        {
            size_t esb = ((size_t)(q0 + qr)) * (S_ / 2) + (k0 >> 1) + 16 * nh + 4 * tig;
            __stcs(reinterpret_cast<uint4*>(&EsW[esb]),
                   make_uint4(pl[0], pl[1], pl[2], pl[3]));
            __stcs(reinterpret_cast<uint4*>(&EsW[esb + 8 * (S_ / 2)]),
                   make_uint4(ph[0], ph[1], ph[2], ph[3]));
        }

        // ---- O phase: fp16 m16n8k16, A = packed P frags (no smem roundtrip)
        #pragma unroll
        for (int c = 0; c < 2; c++) {
            uint32_t ap[4] = { pl[2 * c], ph[2 * c], pl[2 * c + 1], ph[2 * c + 1] };
            int kwb = 16 * nh + 8 * c;   // key word base within tile
            #pragma unroll
            for (int nj = 0; nj < 4; nj++) {
                uint32_t bv[2];
                int drow = 8 * nj + gid;
                bv[0] = Vs[drow * 36 + kwb + tig];
                bv[1] = Vs[drow * 36 + kwb + tig + 4];
                mma_f16(oacc[nj], ap, bv, oacc[nj]);
            }
        }
    }

    // ---- reduce row sums; linv to smem + gmem
    __syncthreads();
    atomicAdd(&lsum[16 * mw + gid], l0);
    atomicAdd(&lsum[16 * mw + gid + 8], l1);
    __syncthreads();
    if (tid < 64) {
        float li = 1.0f / lsum[tid];
        linv[tid] = li;
        g_linv[(size_t)bh * S_ + q0 + tid] = li;
    }
    __syncthreads();

    // ---- combine nh warp pairs, normalize, write ctx
    if (nh == 1) {
        #pragma unroll
        for (int nj = 0; nj < 4; nj++) {
            float* rb = &redO[((mw * 4 + nj) * 16) * 8];
            rb[gid * 8 + 2 * tig]           = oacc[nj][0];
            rb[gid * 8 + 2 * tig + 1]       = oacc[nj][1];
            rb[(gid + 8) * 8 + 2 * tig]     = oacc[nj][2];
            rb[(gid + 8) * 8 + 2 * tig + 1] = oacc[nj][3];
        }
    }
    __syncthreads();
    if (nh == 0) {
        int qr = 16 * mw + gid;
        float li0 = linv[qr], li1 = linv[qr + 8];
        #pragma unroll
        for (int nj = 0; nj < 4; nj++) {
            const float* rb = &redO[((mw * 4 + nj) * 16) * 8];
            float o0 = (oacc[nj][0] + rb[gid * 8 + 2 * tig]) * li0;
            float o1 = (oacc[nj][1] + rb[gid * 8 + 2 * tig + 1]) * li0;
            float o2 = (oacc[nj][2] + rb[(gid + 8) * 8 + 2 * tig]) * li1;
            float o3 = (oacc[nj][3] + rb[(gid + 8) * 8 + 2 * tig + 1]) * li1;
            int d = h * HD_ + 8 * nj + 2 * tig;
            *reinterpret_cast<float2*>(
                &g_ctx[((size_t)b * S_ + q0 + qr) * E_ + d]) = make_float2(o0, o1);
            *reinterpret_cast<float2*>(
                &g_ctx[((size_t)b * S_ + q0 + qr + 8) * E_ + d]) = make_float2(o2, o3);
        }
    }
}

// ---------------- kernel 3: attn map column sums from streamed e ----------------
// out_attn[b][k] = (1/8192) * sum_{h,q} e[bh][q][k] * linv[bh][q]
// grid (8, 128), block 256: thread owns one uint4 column over 32 rows.
// Permuted layout inversion: thread's uint4 at word base 4*col, j-th element ->
// keypair kp0 + 4*j, kp0 = (col>>2)*16 + (col&3).
__global__ void __launch_bounds__(256) k_amap(float* __restrict__ out_attn) {
    int b = blockIdx.x;
    int rc = blockIdx.y;                 // 128 chunks of 64 rows
    int col = threadIdx.x & 127;         // uint4 column (0..127)
    int rh = threadIdx.x >> 7;           // row half (0/1)
    const uint4* Eb = reinterpret_cast<const uint4*>(
        g_Es + ((size_t)b * NH_ * S_) * (S_ / 2));
    const float* Lb = g_linv + (size_t)b * NH_ * S_;
    int row0 = rc * 64 + rh * 32;
    float a0 = 0.f, a1 = 0.f, a2 = 0.f, a3 = 0.f;
    float b0 = 0.f, b1 = 0.f, b2 = 0.f, b3 = 0.f;
    #pragma unroll 8
    for (int i = 0; i < 32; i++) {
        int rr = row0 + i;
        float li = Lb[rr];
        uint4 u = __ldcs(&Eb[(size_t)rr * 128 + col]);
        float2 f0 = __half22float2(*reinterpret_cast<__half2*>(&u.x));
        float2 f1 = __half22float2(*reinterpret_cast<__half2*>(&u.y));
        float2 f2 = __half22float2(*reinterpret_cast<__half2*>(&u.z));
        float2 f3 = __half22float2(*reinterpret_cast<__half2*>(&u.w));
        a0 = fmaf(f0.x, li, a0); b0 = fmaf(f0.y, li, b0);
        a1 = fmaf(f1.x, li, a1); b1 = fmaf(f1.y, li, b1);
        a2 = fmaf(f2.x, li, a2); b2 = fmaf(f2.y, li, b2);
        a3 = fmaf(f3.x, li, a3); b3 = fmaf(f3.y, li, b3);
    }
    int kp0 = ((col >> 2) << 4) + (col & 3);
    const float sc = 1.0f / 8192.0f;
    float* oa = out_attn + b * S_;
    atomicAdd(&oa[2 * (kp0 + 0)],      a0 * sc);
    atomicAdd(&oa[2 * (kp0 + 0) + 1],  b0 * sc);
    atomicAdd(&oa[2 * (kp0 + 4)],      a1 * sc);
    atomicAdd(&oa[2 * (kp0 + 4) + 1],  b1 * sc);
    atomicAdd(&oa[2 * (kp0 + 8)],      a2 * sc);
    atomicAdd(&oa[2 * (kp0 + 8) + 1],  b2 * sc);
    atomicAdd(&oa[2 * (kp0 + 12)],     a3 * sc);
    atomicAdd(&oa[2 * (kp0 + 12) + 1], b3 * sc);
}

// ---------------- kernel 4: fuse + BN + SiLU + residual, tf32 MMA ----------------
__global__ void __launch_bounds__(256) k_fuse(const float* __restrict__ tgt,
                       const float* __restrict__ gamma,
                       const float* __restrict__ beta,
                       const float* __restrict__ mean,
                       const float* __restrict__ var,
                       float* __restrict__ out) {
    __shared__ uint32_t As[64 * 36];  // Mw bits [c][e-chunk]
    __shared__ uint32_t Bs[64 * 36];  // ctx bits [s][e-chunk]
    int b = blockIdx.z;
    int c0 = blockIdx.x * 64, s0 = blockIdx.y * 64;
    const float* Cb = g_ctx + (size_t)b * S_ * E_;
    int tid = threadIdx.x;
    int lane = tid & 31, w = tid >> 5;
    int gid = lane >> 2, tig = lane & 3;
    int mw = w >> 1, nh = w & 1;
    int el = tid & 31, rl0 = tid >> 5;

    float acc[4][4] = {};
    #pragma unroll 1
    for (int ch = 0; ch < 8; ch++) {
        int e0 = ch << 5;
        __syncthreads();
        #pragma unroll
        for (int r = 0; r < 8; r++) {
            int row = rl0 + 8 * r;
            As[row * 36 + el] = g_Mw_t[(size_t)(c0 + row) * E_ + e0 + el];
            Bs[row * 36 + el] = f2tf32(Cb[(size_t)(s0 + row) * E_ + e0 + el]);
        }
        __syncthreads();
        #pragma unroll
        for (int ks = 0; ks < 4; ks++) {
            uint32_t a[4];
            int cr = 16 * mw + gid;
            int ec = 8 * ks + tig;
            a[0] = As[cr * 36 + ec];
            a[1] = As[(cr + 8) * 36 + ec];
            a[2] = As[cr * 36 + ec + 4];
            a[3] = As[(cr + 8) * 36 + ec + 4];
            #pragma unroll
            for (int nt = 0; nt < 4; nt++) {
                uint32_t bb[2];
                int sr = 32 * nh + 8 * nt + gid;
                bb[0] = Bs[sr * 36 + ec];
                bb[1] = Bs[sr * 36 + ec + 4];
                mma_tf32(acc[nt], a, bb, acc[nt]);
            }
        }
    }
    int c = c0 + 16 * mw + gid;
    float inv0 = gamma[c] * rsqrtf(var[c] + 1e-5f);
    float mu0 = mean[c], bet0 = beta[c], fb0 = g_fb[c];
    float inv1 = gamma[c + 8] * rsqrtf(var[c + 8] + 1e-5f);
    float mu1 = mean[c + 8], bet1 = beta[c + 8], fb1 = g_fb[c + 8];
    #pragma unroll
    for (int nt = 0; nt < 4; nt++) {
        int s = s0 + 32 * nh + 8 * nt + 2 * tig;
        size_t off0 = (size_t)b * (CT_ * S_) + (size_t)c * S_ + s;
        size_t off1 = off0 + (size_t)8 * S_;
        float2 t0 = *reinterpret_cast<const float2*>(&tgt[off0]);
        float2 t1 = *reinterpret_cast<const float2*>(&tgt[off1]);
        float bn, sg;
        float2 y0, y1;
        bn = (acc[nt][0] + fb0 - mu0) * inv0 + bet0;
        sg = 1.0f / (1.0f + __expf(-bn)); y0.x = t0.x + bn * sg;
        bn = (acc[nt][1] + fb0 - mu0) * inv0 + bet0;
        sg = 1.0f / (1.0f + __expf(-bn)); y0.y = t0.y + bn * sg;
        bn = (acc[nt][2] + fb1 - mu1) * inv1 + bet1;
        sg = 1.0f / (1.0f + __expf(-bn)); y1.x = t1.x + bn * sg;
        bn = (acc[nt][3] + fb1 - mu1) * inv1 + bet1;
        sg = 1.0f / (1.0f + __expf(-bn)); y1.y = t1.y + bn * sg;
        *reinterpret_cast<float2*>(&out[off0]) = y0;
        *reinterpret_cast<float2*>(&out[off1]) = y1;
    }
}

// ---------------- host launch ----------------
extern "C" void kernel_launch(void* const* d_in, const int* in_sizes, int n_in,
                              void* d_out, int out_size) {
    const float* tgt        = (const float*)d_in[0];
    const float* src        = (const float*)d_in[1];
    const float* kv_w       = (const float*)d_in[2];
    const float* in_proj_w  = (const float*)d_in[3];
    const float* in_proj_b  = (const float*)d_in[4];
    const float* out_proj_w = (const float*)d_in[5];
    const float* out_proj_b = (const float*)d_in[6];
    const float* fuse_w     = (const float*)d_in[7];
    const float* bn_gamma   = (const float*)d_in[8];
    const float* bn_beta    = (const float*)d_in[9];
    const float* bn_mean    = (const float*)d_in[10];
    const float* bn_var     = (const float*)d_in[11];

    float* out_y    = (float*)d_out;                         // B*Ct*H*W
    float* out_attn = (float*)d_out + (size_t)B_ * CT_ * S_; // B*H*W

    static const int ATTN_SMEM = 31744;

    // 0. fold weights -> tf32 bit matrices, zero attn map
    k_combine<<<(205056 + 255) / 256, 256>>>(in_proj_w, kv_w, fuse_w,
                                             out_proj_w, out_proj_b, out_attn);

    // 1. Q/K/V projections in one launch (tf32 MMA)
    dim3 gp(S_ / 64, E_ / 64, 3 * B_);
    k_proj<<<gp, 256>>>(tgt, src, in_proj_b);

    // 2. fused single-pass tensor-core attention (streams e + linv to gmem)
    dim3 ga(S_ / 64, B_ * NH_);
    k_attn<<<ga, 256, ATTN_SMEM>>>();

    // 3. attn map column sums (bandwidth-optimized, 4x parallelism)
    dim3 gm(B_, 128);
    k_amap<<<gm, 256>>>(out_attn);

    // 4. fuse + BN + SiLU + residual (tf32 MMA)
    dim3 gf(CT_ / 64, S_ / 64, B_);
    k_fuse<<<gf, 256>>>(tgt, bn_gamma, bn_beta, bn_mean, bn_var, out_y);
}

// round 16
// speedup vs baseline: 1.4281x; 1.0627x over previous
#include <cuda_runtime.h>
#include <cuda_fp16.h>
#include <cstdint>
#include <math.h>

// Problem constants
#define B_   8
#define S_   1024      // H*W
#define E_   256
#define CS_  128
#define CT_  256
#define NH_  8
#define HD_  32

// ---------------- scratch (static device memory; no allocations) ----------------
__device__ uint32_t g_Wq_t [E_ * E_];        // tf32 bits of in_proj_w[:E]
__device__ uint32_t g_Wk2_t[E_ * CS_];       // tf32 bits of Wk @ kv_w
__device__ uint32_t g_Wv2_t[E_ * CS_];       // tf32 bits of Wv @ kv_w
__device__ uint32_t g_Mw_t [CT_ * E_];       // tf32 bits of fuse_w @ out_proj_w
__device__ float    g_fb   [CT_];            // fuse_w @ out_proj_b
__device__ uint32_t g_Q  [B_ * NH_ * S_ * HD_]; // tf32 bits, [b][h][s][d]
__device__ uint32_t g_K  [B_ * NH_ * S_ * HD_];
__device__ __half   g_Vh [B_ * NH_ * HD_ * S_]; // fp16, TRANSPOSED [b][h][d][s]
__device__ float    g_ctx[B_ * S_ * E_];        // [b][s][e] fp32
__device__ float    g_linv[B_ * NH_ * S_];      // 1/l per (bh, q)
// fp16x2 unnormalized e, PERMUTED within each 16-word group: stored pos = 4*tig+nt
__device__ uint32_t g_Es[(size_t)B_ * NH_ * S_ * S_ / 2];

// ---------------- helpers ----------------
__device__ __forceinline__ uint32_t f2tf32(float x) {
    uint32_t r;
    asm("cvt.rna.tf32.f32 %0, %1;" : "=r"(r) : "f"(x));
    return r;
}
__device__ __forceinline__ void mma_tf32(float d[4], const uint32_t a[4],
                                         const uint32_t b[2], const float c[4]) {
    asm volatile(
        "mma.sync.aligned.m16n8k8.row.col.f32.tf32.tf32.f32 "
        "{%0,%1,%2,%3}, {%4,%5,%6,%7}, {%8,%9}, {%10,%11,%12,%13};"
        : "=f"(d[0]), "=f"(d[1]), "=f"(d[2]), "=f"(d[3])
        : "r"(a[0]), "r"(a[1]), "r"(a[2]), "r"(a[3]),
          "r"(b[0]), "r"(b[1]),
          "f"(c[0]), "f"(c[1]), "f"(c[2]), "f"(c[3]));
}
__device__ __forceinline__ void mma_f16(float d[4], const uint32_t a[4],
                                        const uint32_t b[2], const float c[4]) {
    asm volatile(
        "mma.sync.aligned.m16n8k16.row.col.f32.f16.f16.f32 "
        "{%0,%1,%2,%3}, {%4,%5,%6,%7}, {%8,%9}, {%10,%11,%12,%13};"
        : "=f"(d[0]), "=f"(d[1]), "=f"(d[2]), "=f"(d[3])
        : "r"(a[0]), "r"(a[1]), "r"(a[2]), "r"(a[3]),
          "r"(b[0]), "r"(b[1]),
          "f"(c[0]), "f"(c[1]), "f"(c[2]), "f"(c[3]));
}
__device__ __forceinline__ uint32_t pack_h2(float lo, float hi) {
    __half2 h = __floats2half2_rn(lo, hi);
    return *reinterpret_cast<uint32_t*>(&h);
}

// ---------------- kernel 0: fold weight chains -> tf32 bits, zero attn map ----------------
__global__ void k_combine(const float* __restrict__ in_proj_w,
                          const float* __restrict__ kv_w,
                          const float* __restrict__ fuse_w,
                          const float* __restrict__ out_proj_w,
                          const float* __restrict__ out_proj_b,
                          float* __restrict__ out_attn) {
    int idx = blockIdx.x * blockDim.x + threadIdx.x;
    const int N1 = E_ * CS_;          // 32768  Wk2
    const int N2 = 2 * N1;            // 65536  Wv2
    const int N3 = N2 + CT_ * E_;     // 131072 Mw
    const int N4 = N3 + CT_;          // 131328 fb
    const int N5 = N4 + E_ * E_;      // 196864 Wq bits
    const int N6 = N5 + B_ * S_;      // 205056 attn zero
    if (idx < N1) {
        int f = idx / CS_, c = idx % CS_;
        float s = 0.f;
        for (int e = 0; e < E_; e++)
            s += in_proj_w[(E_ + f) * E_ + e] * kv_w[e * CS_ + c];
        g_Wk2_t[idx] = f2tf32(s);
    } else if (idx < N2) {
        int j = idx - N1;
        int f = j / CS_, c = j % CS_;
        float s = 0.f;
        for (int e = 0; e < E_; e++)
            s += in_proj_w[(2 * E_ + f) * E_ + e] * kv_w[e * CS_ + c];
        g_Wv2_t[j] = f2tf32(s);
    } else if (idx < N3) {
        int j = idx - N2;
        int cc = j / E_, ep = j % E_;
        float s = 0.f;
        for (int e = 0; e < E_; e++)
            s += fuse_w[cc * E_ + e] * out_proj_w[e * E_ + ep];
        g_Mw_t[j] = f2tf32(s);
    } else if (idx < N4) {
        int cc = idx - N3;
        float s = 0.f;
        for (int e = 0; e < E_; e++)
            s += fuse_w[cc * E_ + e] * out_proj_b[e];
        g_fb[cc] = s;
    } else if (idx < N5) {
        int j = idx - N4;
        g_Wq_t[j] = f2tf32(in_proj_w[j]);
    } else if (idx < N6) {
        out_attn[idx - N5] = 0.f;
    }
}

// ---------------- kernel 1: Q/K/V projection, tf32 MMA (merged 3-way) ----------------
// blockIdx.z: which = z>>3 (0=Q,1=K,2=V), b = z&7
// Q,K stored as tf32 bits [bh][s][d]; V stored fp16 TRANSPOSED [bh][d][s].
__global__ void __launch_bounds__(256) k_proj(const float* __restrict__ tgt,
                                              const float* __restrict__ src,
                                              const float* __restrict__ in_proj_b) {
    __shared__ uint32_t As[32 * 68];   // [c][s] tf32 bits
    __shared__ uint32_t Bs[64 * 36];   // [e][c] tf32 bits
    int which = blockIdx.z >> 3;
    int b = blockIdx.z & 7;
    const uint32_t* W = (which == 0) ? g_Wq_t : (which == 1 ? g_Wk2_t : g_Wv2_t);
    const float* In = (which == 0) ? tgt : src;
    const float* bias = in_proj_b + which * E_;
    int Cin = (which == 0) ? CT_ : CS_;

    int s0 = blockIdx.x * 64, e0 = blockIdx.y * 64;
    int tid = threadIdx.x;
    int lane = tid & 31, w = tid >> 5;
    int gid = lane >> 2, tig = lane & 3;
    int mw = w >> 1, nh = w & 1;   // s block of 16, e half of 32
    const float* Ab = In + (size_t)b * Cin * S_;

    int sl = tid & 63, cl0 = tid >> 6;    // A loader coords
    int clB = tid & 31, el0 = tid >> 5;   // B loader coords

    float acc[4][4] = {};
    int nchunks = Cin >> 5;
    for (int ch = 0; ch < nchunks; ch++) {
        int c0 = ch << 5;
        __syncthreads();
        #pragma unroll
        for (int r = 0; r < 8; r++) {
            int cl = cl0 + 4 * r;
            As[cl * 68 + sl] = f2tf32(Ab[(size_t)(c0 + cl) * S_ + s0 + sl]);
        }
        #pragma unroll
        for (int r = 0; r < 8; r++) {
            int el = el0 + 8 * r;
            Bs[el * 36 + clB] = W[(size_t)(e0 + el) * Cin + c0 + clB];
        }
        __syncthreads();
        #pragma unroll
        for (int ks = 0; ks < 4; ks++) {
            uint32_t a[4];
            int sr = 16 * mw + gid;
            int cc = 8 * ks + tig;
            a[0] = As[cc * 68 + sr];
            a[1] = As[cc * 68 + sr + 8];
            a[2] = As[(cc + 4) * 68 + sr];
            a[3] = As[(cc + 4) * 68 + sr + 8];
            #pragma unroll
            for (int nt = 0; nt < 4; nt++) {
                uint32_t bb[2];
                int er = 32 * nh + 8 * nt + gid;
                bb[0] = Bs[er * 36 + 8 * ks + tig];
                bb[1] = Bs[er * 36 + 8 * ks + tig + 4];
                mma_tf32(acc[nt], a, bb, acc[nt]);
            }
        }
    }
    // epilogue
    if (which != 2) {
        uint32_t* Out = (which == 0) ? g_Q : g_K;
        #pragma unroll
        for (int nt = 0; nt < 4; nt++) {
            int e = e0 + 32 * nh + 8 * nt + 2 * tig;
            float b0 = bias[e], b1 = bias[e + 1];
            int h = e >> 5, d = e & 31;
            int s = s0 + 16 * mw + gid;
            uint32_t lo, hi;
            size_t base = (((size_t)(b * NH_ + h) * S_ + s) << 5) + d;
            lo = f2tf32(acc[nt][0] + b0); hi = f2tf32(acc[nt][1] + b1);
            *reinterpret_cast<uint2*>(&Out[base]) = make_uint2(lo, hi);
            lo = f2tf32(acc[nt][2] + b0); hi = f2tf32(acc[nt][3] + b1);
            *reinterpret_cast<uint2*>(&Out[base + (8u << 5)]) = make_uint2(lo, hi);
        }
    } else {
        // V: fp16 transposed [bh][d][s]
        #pragma unroll
        for (int nt = 0; nt < 4; nt++) {
            int e = e0 + 32 * nh + 8 * nt + 2 * tig;
            float b0 = bias[e], b1 = bias[e + 1];
            int h = e >> 5, d = e & 31;
            int s = s0 + 16 * mw + gid;
            size_t r0 = ((size_t)(b * NH_ + h) * HD_ + d) * S_;
            size_t r1 = r0 + S_;   // d+1 row (same head: d = 8nt+2tig <= 30)
            g_Vh[r0 + s]     = __float2half(acc[nt][0] + b0);
            g_Vh[r1 + s]     = __float2half(acc[nt][1] + b1);
            g_Vh[r0 + s + 8] = __float2half(acc[nt][2] + b0);
            g_Vh[r1 + s + 8] = __float2half(acc[nt][3] + b1);
        }
    }
}

// ---------------- kernel 2: fused attention, single pass, register P ----------------
// S = QK^T in tf32 MMA; exp in regs; P packed fp16x2 feeds m16n8k16 O-MMA directly.
// Unnormalized e streamed to g_Es via ONE uint4 STG.128 per row-half (permuted layout:
// within each 16-word group, stored position = 4*tig + nt for keypair word 4*nt + tig).
// smem words: Qs[64*36]@0, Ks[64*36]@2304, Vs[32*36]@4608, lsum@5760, linv@5824, redO@5888[2048]
// total 7936 words = 31744 B
__global__ void __launch_bounds__(256, 2) k_attn() {
    extern __shared__ uint32_t sm[];
    uint32_t* Qs = sm;
    uint32_t* Ks = sm + 2304;
    uint32_t* Vs = sm + 4608;           // [d][key-pair words], stride 36
    float* lsum  = (float*)(sm + 5760);
    float* linv  = (float*)(sm + 5824);
    float* redO  = (float*)(sm + 5888); // [mw][nj][16][8]

    int bh = blockIdx.y;
    int b = bh >> 3, h = bh & 7;
    int q0 = blockIdx.x * 64;
    const uint32_t* Qb = g_Q + (size_t)bh * S_ * HD_;
    const uint32_t* Kb = g_K + (size_t)bh * S_ * HD_;
    const uint32_t* VhW = reinterpret_cast<const uint32_t*>(g_Vh) + (size_t)bh * HD_ * (S_ / 2);
    uint32_t* EsW = g_Es + ((size_t)bh * S_ * S_ / 2);

    int tid = threadIdx.x;
    int lane = tid & 31, w = tid >> 5;
    int gid = lane >> 2, tig = lane & 3;
    int r8 = tid >> 5, d32 = tid & 31;      // K loader coords
    int vd = tid >> 3, vw0 = tid & 7;       // V loader coords

    int mw = w >> 1, nh = w & 1;

    if (tid < 64) lsum[tid] = 0.f;

    #pragma unroll
    for (int r = 0; r < 8; r++) {
        int q = r8 + 8 * r;
        Qs[q * 36 + d32] = Qb[(size_t)(q0 + q) * HD_ + d32];
    }
    __syncthreads();

    // Q fragments, register-resident
    uint32_t aq[4][4];
    #pragma unroll
    for (int ks = 0; ks < 4; ks++) {
        int qr = 16 * mw + gid;
        int c  = ks * 8 + tig;
        aq[ks][0] = Qs[qr * 36 + c];
        aq[ks][1] = Qs[(qr + 8) * 36 + c];
        aq[ks][2] = Qs[qr * 36 + c + 4];
        aq[ks][3] = Qs[(qr + 8) * 36 + c + 4];
    }

    const float scale = 0.17677669529663687f; // 1/sqrt(32)
    float l0 = 0.f, l1 = 0.f;
    float oacc[4][4] = {};   // [nj: d 8-col tile][frag]

    // prefetch tile 0
    uint32_t kreg[8], vreg[4];
    #pragma unroll
    for (int r = 0; r < 8; r++)
        kreg[r] = Kb[(size_t)(r8 + 8 * r) * HD_ + d32];
    #pragma unroll
    for (int r = 0; r < 4; r++)
        vreg[r] = VhW[(size_t)vd * (S_ / 2) + vw0 + 8 * r];

    for (int t = 0; t < 16; t++) {
        int k0 = t * 64;
        __syncthreads();   // prior tile compute done with Ks/Vs
        #pragma unroll
        for (int r = 0; r < 8; r++)
            Ks[(r8 + 8 * r) * 36 + d32] = kreg[r];
        #pragma unroll
        for (int r = 0; r < 4; r++)
            Vs[vd * 36 + vw0 + 8 * r] = vreg[r];
        __syncthreads();
        if (t < 15) {
            int k0n = k0 + 64;
            #pragma unroll
            for (int r = 0; r < 8; r++)
                kreg[r] = Kb[(size_t)(k0n + r8 + 8 * r) * HD_ + d32];
            #pragma unroll
            for (int r = 0; r < 4; r++)
                vreg[r] = VhW[(size_t)vd * (S_ / 2) + (k0n >> 1) + vw0 + 8 * r];
        }

        // ---- S phase: tf32 MMA over this warp's 32-key half
        float sacc[4][4] = {};
        #pragma unroll
        for (int ks = 0; ks < 4; ks++) {
            #pragma unroll
            for (int nt = 0; nt < 4; nt++) {
                uint32_t bf[2];
                int key = 32 * nh + 8 * nt + gid;
                int d0  = ks * 8 + tig;
                bf[0] = Ks[key * 36 + d0];
                bf[1] = Ks[key * 36 + d0 + 4];
                mma_tf32(sacc[nt], aq[ks], bf, sacc[nt]);
            }
        }

        // ---- exp + pack + row-sum partials
        uint32_t pl[4], ph[4];
        int qr = 16 * mw + gid;
        #pragma unroll
        for (int nt = 0; nt < 4; nt++) {
            float e0 = __expf(sacc[nt][0] * scale);
            float e1 = __expf(sacc[nt][1] * scale);
            float e2 = __expf(sacc[nt][2] * scale);
            float e3 = __expf(sacc[nt][3] * scale);
            l0 += e0 + e1;
            l1 += e2 + e3;
            pl[nt] = pack_h2(e0, e1);
            ph[nt] = pack_h2(e2, e3);
        }
        // stream to gmem: permuted layout -> one STG.128 per row-half
        {
            size_t esb = ((size_t)(q0 + qr)) * (S_ / 2) + (k0 >> 1) + 16 * nh + 4 * tig;
            __stcs(reinterpret_cast<uint4*>(&EsW[esb]),
                   make_uint4(pl[0], pl[1], pl[2], pl[3]));
            __stcs(reinterpret_cast<uint4*>(&EsW[esb + 8 * (S_ / 2)]),
                   make_uint4(ph[0], ph[1], ph[2], ph[3]));
        }

        // ---- O phase: fp16 m16n8k16, A = packed P frags (no smem roundtrip)
        #pragma unroll
        for (int c = 0; c < 2; c++) {
            uint32_t ap[4] = { pl[2 * c], ph[2 * c], pl[2 * c + 1], ph[2 * c + 1] };
            int kwb = 16 * nh + 8 * c;   // key word base within tile
            #pragma unroll
            for (int nj = 0; nj < 4; nj++) {
                uint32_t bv[2];
                int drow = 8 * nj + gid;
                bv[0] = Vs[drow * 36 + kwb + tig];
                bv[1] = Vs[drow * 36 + kwb + tig + 4];
                mma_f16(oacc[nj], ap, bv, oacc[nj]);
            }
        }
    }

    // ---- reduce row sums; linv to smem + gmem
    __syncthreads();
    atomicAdd(&lsum[16 * mw + gid], l0);
    atomicAdd(&lsum[16 * mw + gid + 8], l1);
    __syncthreads();
    if (tid < 64) {
        float li = 1.0f / lsum[tid];
        linv[tid] = li;
        g_linv[(size_t)bh * S_ + q0 + tid] = li;
    }
    __syncthreads();

    // ---- combine nh warp pairs, normalize, write ctx
    if (nh == 1) {
        #pragma unroll
        for (int nj = 0; nj < 4; nj++) {
            float* rb = &redO[((mw * 4 + nj) * 16) * 8];
            rb[gid * 8 + 2 * tig]           = oacc[nj][0];
            rb[gid * 8 + 2 * tig + 1]       = oacc[nj][1];
            rb[(gid + 8) * 8 + 2 * tig]     = oacc[nj][2];
            rb[(gid + 8) * 8 + 2 * tig + 1] = oacc[nj][3];
        }
    }
    __syncthreads();
    if (nh == 0) {
        int qr = 16 * mw + gid;
        float li0 = linv[qr], li1 = linv[qr + 8];
        #pragma unroll
        for (int nj = 0; nj < 4; nj++) {
            const float* rb = &redO[((mw * 4 + nj) * 16) * 8];
            float o0 = (oacc[nj][0] + rb[gid * 8 + 2 * tig]) * li0;
            float o1 = (oacc[nj][1] + rb[gid * 8 + 2 * tig + 1]) * li0;
            float o2 = (oacc[nj][2] + rb[(gid + 8) * 8 + 2 * tig]) * li1;
            float o3 = (oacc[nj][3] + rb[(gid + 8) * 8 + 2 * tig + 1]) * li1;
            int d = h * HD_ + 8 * nj + 2 * tig;
            *reinterpret_cast<float2*>(
                &g_ctx[((size_t)b * S_ + q0 + qr) * E_ + d]) = make_float2(o0, o1);
            *reinterpret_cast<float2*>(
                &g_ctx[((size_t)b * S_ + q0 + qr + 8) * E_ + d]) = make_float2(o2, o3);
        }
    }
}

// ---------------- kernel 3: attn map column sums from streamed e ----------------
// out_attn[b][k] = (1/8192) * sum_{h,q} e[bh][q][k] * linv[bh][q]
// grid (8, 256), block 256: CTA covers 32 rows; thread = one uint4 column over 16 rows
// (rh selects row half). Loads batched in groups of 4 (structural MLP=4); linv via smem;
// row-half partials combined in smem so only 128 threads/CTA issue gmem atomics.
// Permuted layout inversion: thread's uint4 at word base 4*col, j-th element ->
// keypair kp0 + 4*j, kp0 = (col>>2)*16 + (col&3).
__global__ void __launch_bounds__(256) k_amap(float* __restrict__ out_attn) {
    __shared__ float li_s[32];
    __shared__ float red[128 * 8];
    int b = blockIdx.x;
    int rc = blockIdx.y;                 // 256 chunks of 32 rows
    int col = threadIdx.x & 127;         // uint4 column (0..127)
    int rh = threadIdx.x >> 7;           // row half (0/1)
    const uint4* Eb = reinterpret_cast<const uint4*>(
        g_Es + ((size_t)b * NH_ * S_) * (S_ / 2));
    const float* Lb = g_linv + (size_t)b * NH_ * S_;
    int row0 = rc * 32;
    if (threadIdx.x < 32) li_s[threadIdx.x] = Lb[row0 + threadIdx.x];
    __syncthreads();

    int rbase = rh * 16;
    float a0 = 0.f, a1 = 0.f, a2 = 0.f, a3 = 0.f;
    float b0 = 0.f, b1 = 0.f, b2 = 0.f, b3 = 0.f;
    #pragma unroll
    for (int i0 = 0; i0 < 16; i0 += 4) {
        // batch 4 independent loads before consuming (structural MLP = 4)
        const uint4* p = &Eb[(size_t)(row0 + rbase + i0) * 128 + col];
        uint4 u0 = __ldcs(p);
        uint4 u1 = __ldcs(p + 128);
        uint4 u2 = __ldcs(p + 256);
        uint4 u3 = __ldcs(p + 384);
        float l0 = li_s[rbase + i0], l1 = li_s[rbase + i0 + 1];
        float l2 = li_s[rbase + i0 + 2], l3 = li_s[rbase + i0 + 3];
        float2 f;
        f = __half22float2(*reinterpret_cast<__half2*>(&u0.x)); a0 = fmaf(f.x, l0, a0); b0 = fmaf(f.y, l0, b0);
        f = __half22float2(*reinterpret_cast<__half2*>(&u0.y)); a1 = fmaf(f.x, l0, a1); b1 = fmaf(f.y, l0, b1);
        f = __half22float2(*reinterpret_cast<__half2*>(&u0.z)); a2 = fmaf(f.x, l0, a2); b2 = fmaf(f.y, l0, b2);
        f = __half22float2(*reinterpret_cast<__half2*>(&u0.w)); a3 = fmaf(f.x, l0, a3); b3 = fmaf(f.y, l0, b3);
        f = __half22float2(*reinterpret_cast<__half2*>(&u1.x)); a0 = fmaf(f.x, l1, a0); b0 = fmaf(f.y, l1, b0);
        f = __half22float2(*reinterpret_cast<__half2*>(&u1.y)); a1 = fmaf(f.x, l1, a1); b1 = fmaf(f.y, l1, b1);
        f = __half22float2(*reinterpret_cast<__half2*>(&u1.z)); a2 = fmaf(f.x, l1, a2); b2 = fmaf(f.y, l1, b2);
        f = __half22float2(*reinterpret_cast<__half2*>(&u1.w)); a3 = fmaf(f.x, l1, a3); b3 = fmaf(f.y, l1, b3);
        f = __half22float2(*reinterpret_cast<__half2*>(&u2.x)); a0 = fmaf(f.x, l2, a0); b0 = fmaf(f.y, l2, b0);
        f = __half22float2(*reinterpret_cast<__half2*>(&u2.y)); a1 = fmaf(f.x, l2, a1); b1 = fmaf(f.y, l2, b1);
        f = __half22float2(*reinterpret_cast<__half2*>(&u2.z)); a2 = fmaf(f.x, l2, a2); b2 = fmaf(f.y, l2, b2);
        f = __half22float2(*reinterpret_cast<__half2*>(&u2.w)); a3 = fmaf(f.x, l2, a3); b3 = fmaf(f.y, l2, b3);
        f = __half22float2(*reinterpret_cast<__half2*>(&u3.x)); a0 = fmaf(f.x, l3, a0); b0 = fmaf(f.y, l3, b0);
        f = __half22float2(*reinterpret_cast<__half2*>(&u3.y)); a1 = fmaf(f.x, l3, a1); b1 = fmaf(f.y, l3, b1);
        f = __half22float2(*reinterpret_cast<__half2*>(&u3.z)); a2 = fmaf(f.x, l3, a2); b2 = fmaf(f.y, l3, b2);
        f = __half22float2(*reinterpret_cast<__half2*>(&u3.w)); a3 = fmaf(f.x, l3, a3); b3 = fmaf(f.y, l3, b3);
    }

    // combine the two row-half threads through smem; only rh==0 issues atomics
    if (rh == 1) {
        float* rb = &red[col * 8];
        rb[0] = a0; rb[1] = b0; rb[2] = a1; rb[3] = b1;
        rb[4] = a2; rb[5] = b2; rb[6] = a3; rb[7] = b3;
    }
    __syncthreads();
    if (rh == 0) {
        const float* rb = &red[col * 8];
        a0 += rb[0]; b0 += rb[1]; a1 += rb[2]; b1 += rb[3];
        a2 += rb[4]; b2 += rb[5]; a3 += rb[6]; b3 += rb[7];
        int kp0 = ((col >> 2) << 4) + (col & 3);
        const float sc = 1.0f / 8192.0f;
        float* oa = out_attn + b * S_;
        atomicAdd(&oa[2 * (kp0 + 0)],      a0 * sc);
        atomicAdd(&oa[2 * (kp0 + 0) + 1],  b0 * sc);
        atomicAdd(&oa[2 * (kp0 + 4)],      a1 * sc);
        atomicAdd(&oa[2 * (kp0 + 4) + 1],  b1 * sc);
        atomicAdd(&oa[2 * (kp0 + 8)],      a2 * sc);
        atomicAdd(&oa[2 * (kp0 + 8) + 1],  b2 * sc);
        atomicAdd(&oa[2 * (kp0 + 12)],     a3 * sc);
        atomicAdd(&oa[2 * (kp0 + 12) + 1], b3 * sc);
    }
}

// ---------------- kernel 4: fuse + BN + SiLU + residual, tf32 MMA ----------------
__global__ void __launch_bounds__(256) k_fuse(const float* __restrict__ tgt,
                       const float* __restrict__ gamma,
                       const float* __restrict__ beta,
                       const float* __restrict__ mean,
                       const float* __restrict__ var,
                       float* __restrict__ out) {
    __shared__ uint32_t As[64 * 36];  // Mw bits [c][e-chunk]
    __shared__ uint32_t Bs[64 * 36];  // ctx bits [s][e-chunk]
    int b = blockIdx.z;
    int c0 = blockIdx.x * 64, s0 = blockIdx.y * 64;
    const float* Cb = g_ctx + (size_t)b * S_ * E_;
    int tid = threadIdx.x;
    int lane = tid & 31, w = tid >> 5;
    int gid = lane >> 2, tig = lane & 3;
    int mw = w >> 1, nh = w & 1;
    int el = tid & 31, rl0 = tid >> 5;

    float acc[4][4] = {};
    #pragma unroll 1
    for (int ch = 0; ch < 8; ch++) {
        int e0 = ch << 5;
        __syncthreads();
        #pragma unroll
        for (int r = 0; r < 8; r++) {
            int row = rl0 + 8 * r;
            As[row * 36 + el] = g_Mw_t[(size_t)(c0 + row) * E_ + e0 + el];
            Bs[row * 36 + el] = f2tf32(Cb[(size_t)(s0 + row) * E_ + e0 + el]);
        }
        __syncthreads();
        #pragma unroll
        for (int ks = 0; ks < 4; ks++) {
            uint32_t a[4];
            int cr = 16 * mw + gid;
            int ec = 8 * ks + tig;
            a[0] = As[cr * 36 + ec];
            a[1] = As[(cr + 8) * 36 + ec];
            a[2] = As[cr * 36 + ec + 4];
            a[3] = As[(cr + 8) * 36 + ec + 4];
            #pragma unroll
            for (int nt = 0; nt < 4; nt++) {
                uint32_t bb[2];
                int sr = 32 * nh + 8 * nt + gid;
                bb[0] = Bs[sr * 36 + ec];
                bb[1] = Bs[sr * 36 + ec + 4];
                mma_tf32(acc[nt], a, bb, acc[nt]);
            }
        }
    }
    int c = c0 + 16 * mw + gid;
    float inv0 = gamma[c] * rsqrtf(var[c] + 1e-5f);
    float mu0 = mean[c], bet0 = beta[c], fb0 = g_fb[c];
    float inv1 = gamma[c + 8] * rsqrtf(var[c + 8] + 1e-5f);
    float mu1 = mean[c + 8], bet1 = beta[c + 8], fb1 = g_fb[c + 8];
    #pragma unroll
    for (int nt = 0; nt < 4; nt++) {
        int s = s0 + 32 * nh + 8 * nt + 2 * tig;
        size_t off0 = (size_t)b * (CT_ * S_) + (size_t)c * S_ + s;
        size_t off1 = off0 + (size_t)8 * S_;
        float2 t0 = *reinterpret_cast<const float2*>(&tgt[off0]);
        float2 t1 = *reinterpret_cast<const float2*>(&tgt[off1]);
        float bn, sg;
        float2 y0, y1;
        bn = (acc[nt][0] + fb0 - mu0) * inv0 + bet0;
        sg = 1.0f / (1.0f + __expf(-bn)); y0.x = t0.x + bn * sg;
        bn = (acc[nt][1] + fb0 - mu0) * inv0 + bet0;
        sg = 1.0f / (1.0f + __expf(-bn)); y0.y = t0.y + bn * sg;
        bn = (acc[nt][2] + fb1 - mu1) * inv1 + bet1;
        sg = 1.0f / (1.0f + __expf(-bn)); y1.x = t1.x + bn * sg;
        bn = (acc[nt][3] + fb1 - mu1) * inv1 + bet1;
        sg = 1.0f / (1.0f + __expf(-bn)); y1.y = t1.y + bn * sg;
        *reinterpret_cast<float2*>(&out[off0]) = y0;
        *reinterpret_cast<float2*>(&out[off1]) = y1;
    }
}

// ---------------- host launch ----------------
extern "C" void kernel_launch(void* const* d_in, const int* in_sizes, int n_in,
                              void* d_out, int out_size) {
    const float* tgt        = (const float*)d_in[0];
    const float* src        = (const float*)d_in[1];
    const float* kv_w       = (const float*)d_in[2];
    const float* in_proj_w  = (const float*)d_in[3];
    const float* in_proj_b  = (const float*)d_in[4];
    const float* out_proj_w = (const float*)d_in[5];
    const float* out_proj_b = (const float*)d_in[6];
    const float* fuse_w     = (const float*)d_in[7];
    const float* bn_gamma   = (const float*)d_in[8];
    const float* bn_beta    = (const float*)d_in[9];
    const float* bn_mean    = (const float*)d_in[10];
    const float* bn_var     = (const float*)d_in[11];

    float* out_y    = (float*)d_out;                         // B*Ct*H*W
    float* out_attn = (float*)d_out + (size_t)B_ * CT_ * S_; // B*H*W

    static const int ATTN_SMEM = 31744;

    // 0. fold weights -> tf32 bit matrices, zero attn map
    k_combine<<<(205056 + 255) / 256, 256>>>(in_proj_w, kv_w, fuse_w,
                                             out_proj_w, out_proj_b, out_attn);

    // 1. Q/K/V projections in one launch (tf32 MMA)
    dim3 gp(S_ / 64, E_ / 64, 3 * B_);
    k_proj<<<gp, 256>>>(tgt, src, in_proj_b);

    // 2. fused single-pass tensor-core attention (streams e + linv to gmem)
    dim3 ga(S_ / 64, B_ * NH_);
    k_attn<<<ga, 256, ATTN_SMEM>>>();

    // 3. attn map column sums (latency-optimized: MLP=4 batching, 2048 CTAs)
    dim3 gm(B_, 256);
    k_amap<<<gm, 256>>>(out_attn);

    // 4. fuse + BN + SiLU + residual (tf32 MMA)
    dim3 gf(CT_ / 64, S_ / 64, B_);
    k_fuse<<<gf, 256>>>(tgt, bn_gamma, bn_beta, bn_mean, bn_var, out_y);
}